// round 11
// baseline (speedup 1.0000x reference)
#include <cuda_runtime.h>
#include <cuda_fp16.h>
#include <mma.h>

using namespace nvcuda;

#define NN 100000
#define NN_PAD 100096                     // 782 * 128
#define NH 50048                          // 391 * 128 (pipeline split point)
#define EE 1600000
#define HID 128
#define NC 2
#define BN_EPS 1e-5f
#define SCAN_B 1024
#define SCAN_NB ((NN + SCAN_B - 1) / SCAN_B)   // 98
#define LDS 136                                 // smem leading dim (half)
#define GEMM_SMEM (2 * 128 * LDS * (int)sizeof(__half))   // 69632 B

// ---------------- scratch (device globals; no allocation allowed) ----------------
__device__ __half g_bufH[(size_t)NN * HID];     // GEMM1 output = agg1 input, fp16
__device__ __half g_buf2[(size_t)NN * HID];     // GEMM2 output = agg2 input, fp16
__device__ __half g_abuf[(size_t)NN_PAD * HID]; // agg1 output (h * dinv) = GEMM2 A
__device__ __half g_w1h[HID * HID];
__device__ __half g_w2h[HID * HID];
__device__ float  g_small[NN * NC];             // fused layer-3 row results
__device__ int    g_deg[NN];
__device__ float  g_dinv[NN];
__device__ int    g_rowstart[NN + 1];
__device__ int    g_blocksum[SCAN_NB];
__device__ int    g_blockoff[SCAN_NB];
__device__ int    g_fill[NN];
__device__ int    g_csr[EE];
__device__ float  g_sc1[HID], g_sh1[HID], g_sc2[HID], g_sh2[HID];
__device__ int    g_is64;

// ---------------- edge dtype detection (parallel) ----------------
__global__ void k_detect(const void* __restrict__ ei) {
    int tid = threadIdx.x;   // 32 threads
    const long long* p = (const long long*)ei;
    int bad = 0;
    #pragma unroll
    for (int k = 0; k < 2; k++) {
        long long v = p[(tid * 2 + k) * 997];
        bad |= (v < 0 || v >= NN) ? 1 : 0;
    }
    unsigned m = __ballot_sync(0xffffffffu, bad);
    if (tid == 0) g_is64 = (m == 0) ? 1 : 0;
}

__device__ __forceinline__ int edge_at(const void* ei, size_t idx) {
    if (g_is64) return (int)((const long long*)ei)[idx];
    return ((const int*)ei)[idx];
}

// ---------------- CSR build ----------------
__global__ void k_zero() {
    int i = blockIdx.x * blockDim.x + threadIdx.x;
    if (i < NN) { g_deg[i] = 0; g_fill[i] = 0; }
}

__global__ void k_count(const void* __restrict__ ei) {
    int e = blockIdx.x * blockDim.x + threadIdx.x;
    if (e < EE) atomicAdd(&g_deg[edge_at(ei, (size_t)EE + e)], 1);
}

__global__ void k_scan1() {
    __shared__ int warpsum[32];
    int tid = threadIdx.x;
    int i = blockIdx.x * SCAN_B + tid;
    int v = (i < NN) ? g_deg[i] : 0;
    if (i < NN) g_dinv[i] = rsqrtf((float)(v + 1));   // +1 self-loop
    int lane = tid & 31, warp = tid >> 5;
    int s = v;
    #pragma unroll
    for (int off = 1; off < 32; off <<= 1) {
        int t = __shfl_up_sync(0xffffffffu, s, off);
        if (lane >= off) s += t;
    }
    if (lane == 31) warpsum[warp] = s;
    __syncthreads();
    if (warp == 0) {
        int ws = (lane < SCAN_B / 32) ? warpsum[lane] : 0;
        #pragma unroll
        for (int off = 1; off < 32; off <<= 1) {
            int t = __shfl_up_sync(0xffffffffu, ws, off);
            if (lane >= off) ws += t;
        }
        warpsum[lane] = ws;
    }
    __syncthreads();
    int base = (warp > 0) ? warpsum[warp - 1] : 0;
    if (i < NN) g_rowstart[i] = base + s - v;
    if (tid == SCAN_B - 1) g_blocksum[blockIdx.x] = base + s;
}

__global__ void k_scan2() {
    __shared__ int sh[128];
    int tid = threadIdx.x;
    int v = (tid < SCAN_NB) ? g_blocksum[tid] : 0;
    int lane = tid & 31, warp = tid >> 5;
    int s = v;
    #pragma unroll
    for (int off = 1; off < 32; off <<= 1) {
        int t = __shfl_up_sync(0xffffffffu, s, off);
        if (lane >= off) s += t;
    }
    if (lane == 31) sh[warp] = s;
    __syncthreads();
    if (warp == 0 && lane < 4) {
        int ws = sh[lane];
        #pragma unroll
        for (int off = 1; off < 4; off <<= 1) {
            int t = __shfl_up_sync(0x0000000fu, ws, off);
            if (lane >= off) ws += t;
        }
        sh[lane] = ws;
    }
    __syncthreads();
    int base = (warp > 0) ? sh[warp - 1] : 0;
    if (tid < SCAN_NB) g_blockoff[tid] = base + s - v;
    if (tid == 127) g_rowstart[NN] = base + s;
}

__global__ void k_scan3() {
    int i = blockIdx.x * SCAN_B + threadIdx.x;
    if (i < NN) g_rowstart[i] += g_blockoff[blockIdx.x];
}

__global__ void k_fill(const void* __restrict__ ei) {
    int e = blockIdx.x * blockDim.x + threadIdx.x;
    if (e < EE) {
        int d = edge_at(ei, (size_t)EE + e);
        int s = edge_at(ei, e);
        int p = atomicAdd(&g_fill[d], 1);
        g_csr[g_rowstart[d] + p] = s;
    }
}

// ---------------- BN parameter folding ----------------
__global__ void k_bnparams(const float* __restrict__ b1, const float* __restrict__ ga1,
                           const float* __restrict__ be1, const float* __restrict__ rm1,
                           const float* __restrict__ rv1,
                           const float* __restrict__ b2, const float* __restrict__ ga2,
                           const float* __restrict__ be2, const float* __restrict__ rm2,
                           const float* __restrict__ rv2) {
    int c = threadIdx.x;
    if (c < HID) {
        float s1 = ga1[c] * rsqrtf(rv1[c] + BN_EPS);
        g_sc1[c] = s1;
        g_sh1[c] = (b1[c] - rm1[c]) * s1 + be1[c];
        float s2 = ga2[c] * rsqrtf(rv2[c] + BN_EPS);
        g_sc2[c] = s2;
        g_sh2[c] = (b2[c] - rm2[c]) * s2 + be2[c];
    }
}

__global__ void k_cvt_w(const float* __restrict__ W1, const float* __restrict__ W2) {
    int i = blockIdx.x * blockDim.x + threadIdx.x;
    if (i < HID * HID) g_w1h[i] = __float2half(W1[i]);
    else if (i < 2 * HID * HID) g_w2h[i - HID * HID] = __float2half(W2[i - HID * HID]);
}

// ---------------- tensor-core GEMM, smem-staged 128x128 tile --------------------
// SRC=0: A = x (fp32, scaled by dinv during staging), W = g_w1h, OUT = g_bufH
// SRC=1: A = g_abuf (fp16, already scaled),           W = g_w2h, OUT = g_buf2
// blockOff: tile offset in 128-row units (for pipelined half launches)
template <int SRC>
__global__ void k_gemm_tc(const float* __restrict__ X, int blockOff) {
    extern __shared__ __half smem[];
    __half* sA = smem;                 // [128][LDS]
    __half* sW = smem + 128 * LDS;     // [128][LDS]
    __shared__ __align__(16) float scratch[8][16][20];

    int tid = threadIdx.x;
    int row0 = (blockIdx.x + blockOff) * 128;
    __half* __restrict__ Out = (SRC == 0) ? g_bufH : g_buf2;

    {
        const __half* __restrict__ Wh = (SRC == 0) ? g_w1h : g_w2h;
        for (int i = tid; i < 128 * 16; i += 256) {
            int r = i >> 4, q = i & 15;
            uint4 v = *(const uint4*)&Wh[r * HID + q * 8];
            *(uint4*)&sW[r * LDS + q * 8] = v;
        }
    }
    if (SRC == 0) {
        for (int i = tid; i < 128 * 32; i += 256) {
            int r = i >> 5, q = i & 31;
            int gr = row0 + r;
            __half2 h01, h23;
            if (gr < NN) {
                float4 v = *(const float4*)&X[(size_t)gr * HID + q * 4];
                float d = g_dinv[gr];
                h01 = __floats2half2_rn(v.x * d, v.y * d);
                h23 = __floats2half2_rn(v.z * d, v.w * d);
            } else {
                h01 = __floats2half2_rn(0.f, 0.f);
                h23 = h01;
            }
            uint2 p;
            p.x = *(unsigned int*)&h01;
            p.y = *(unsigned int*)&h23;
            *(uint2*)&sA[r * LDS + q * 4] = p;
        }
    } else {
        for (int i = tid; i < 128 * 16; i += 256) {
            int r = i >> 4, q = i & 15;
            int gr = row0 + r;     // g_abuf padded to NN_PAD with zeros
            uint4 v = *(const uint4*)&g_abuf[(size_t)gr * HID + q * 8];
            *(uint4*)&sA[r * LDS + q * 8] = v;
        }
    }
    __syncthreads();

    int warp = tid >> 5, lane = tid & 31;
    int rg = warp >> 1, cg = warp & 1;
    int wr0 = rg * 32, col0 = cg * 64;

    wmma::fragment<wmma::accumulator, 16, 16, 16, float> c[2][4];
    #pragma unroll
    for (int i = 0; i < 2; i++)
        #pragma unroll
        for (int j = 0; j < 4; j++) wmma::fill_fragment(c[i][j], 0.f);

    #pragma unroll
    for (int k = 0; k < HID; k += 16) {
        wmma::fragment<wmma::matrix_a, 16, 16, 16, __half, wmma::row_major> a[2];
        wmma::fragment<wmma::matrix_b, 16, 16, 16, __half, wmma::row_major> b[4];
        wmma::load_matrix_sync(a[0], sA + (wr0 + 0) * LDS + k, LDS);
        wmma::load_matrix_sync(a[1], sA + (wr0 + 16) * LDS + k, LDS);
        #pragma unroll
        for (int j = 0; j < 4; j++)
            wmma::load_matrix_sync(b[j], sW + k * LDS + col0 + j * 16, LDS);
        #pragma unroll
        for (int i = 0; i < 2; i++)
            #pragma unroll
            for (int j = 0; j < 4; j++)
                wmma::mma_sync(c[i][j], a[i], b[j], c[i][j]);
    }

    #pragma unroll
    for (int i = 0; i < 2; i++) {
        #pragma unroll
        for (int j = 0; j < 4; j++) {
            wmma::store_matrix_sync(&scratch[warp][0][0], c[i][j], 20, wmma::mem_row_major);
            __syncwarp();
            int r = lane >> 1, ch = lane & 1;
            int gr = row0 + wr0 + i * 16 + r;
            if (gr < NN) {
                int gc = col0 + j * 16 + ch * 8;
                const float* s = &scratch[warp][r][ch * 8];
                __half2 h0 = __floats2half2_rn(s[0], s[1]);
                __half2 h1 = __floats2half2_rn(s[2], s[3]);
                __half2 h2 = __floats2half2_rn(s[4], s[5]);
                __half2 h3 = __floats2half2_rn(s[6], s[7]);
                uint4 p;
                p.x = *(unsigned int*)&h0;
                p.y = *(unsigned int*)&h1;
                p.z = *(unsigned int*)&h2;
                p.w = *(unsigned int*)&h3;
                *(uint4*)&Out[(size_t)gr * HID + gc] = p;
            }
            __syncwarp();
        }
    }
}

// ------------- shared gather body (warp per node, uint2, 4-wide unroll) ---------
__device__ __forceinline__ void agg_gather(const __half* __restrict__ B,
                                           int w, int c0, float& ax, float& ay,
                                           float& az, float& aw) {
    int beg = g_rowstart[w], end = g_rowstart[w + 1];
    {
        uint2 p = *(const uint2*)&B[(size_t)w * HID + c0];
        float2 f01 = __half22float2(*(__half2*)&p.x);
        float2 f23 = __half22float2(*(__half2*)&p.y);
        ax = f01.x; ay = f01.y; az = f23.x; aw = f23.y;
    }
    int e = beg;
    for (; e + 4 <= end; e += 4) {
        int s0 = g_csr[e];
        int s1 = g_csr[e + 1];
        int s2 = g_csr[e + 2];
        int s3 = g_csr[e + 3];
        uint2 p0 = *(const uint2*)&B[(size_t)s0 * HID + c0];
        uint2 p1 = *(const uint2*)&B[(size_t)s1 * HID + c0];
        uint2 p2 = *(const uint2*)&B[(size_t)s2 * HID + c0];
        uint2 p3 = *(const uint2*)&B[(size_t)s3 * HID + c0];
        float2 a01 = __half22float2(*(__half2*)&p0.x);
        float2 a23 = __half22float2(*(__half2*)&p0.y);
        float2 b01 = __half22float2(*(__half2*)&p1.x);
        float2 b23 = __half22float2(*(__half2*)&p1.y);
        float2 c01 = __half22float2(*(__half2*)&p2.x);
        float2 c23 = __half22float2(*(__half2*)&p2.y);
        float2 d01 = __half22float2(*(__half2*)&p3.x);
        float2 d23 = __half22float2(*(__half2*)&p3.y);
        ax += (a01.x + b01.x) + (c01.x + d01.x);
        ay += (a01.y + b01.y) + (c01.y + d01.y);
        az += (a23.x + b23.x) + (c23.x + d23.x);
        aw += (a23.y + b23.y) + (c23.y + d23.y);
    }
    for (; e < end; e++) {
        int s0 = g_csr[e];
        uint2 p0 = *(const uint2*)&B[(size_t)s0 * HID + c0];
        float2 a01 = __half22float2(*(__half2*)&p0.x);
        float2 a23 = __half22float2(*(__half2*)&p0.y);
        ax += a01.x; ay += a01.y; az += a23.x; aw += a23.y;
    }
}

// ---------------- agg layer 1: gather g_bufH -> BN/ReLU -> *dinv -> g_abuf ------
// nodeOff: first node this launch covers (for pipelined half launches)
__global__ void k_agg1(int nodeOff, int nodeCnt) {
    int w = nodeOff + ((blockIdx.x * blockDim.x + threadIdx.x) >> 5);
    int lane = threadIdx.x & 31;
    int c0 = lane * 4;
    if (w >= nodeOff + nodeCnt) return;
    if (w >= NN) {
        if (w < NN_PAD) {
            uint2 p;
            p.x = 0u; p.y = 0u;
            *(uint2*)&g_abuf[(size_t)w * HID + c0] = p;
        }
        return;
    }
    float ax, ay, az, aw;
    agg_gather(g_bufH, w, c0, ax, ay, az, aw);
    float d = g_dinv[w];
    float4 s4 = *(const float4*)&g_sc1[c0];
    float4 h4 = *(const float4*)&g_sh1[c0];
    float ox = fmaxf(ax * d * s4.x + h4.x, 0.f) * d;
    float oy = fmaxf(ay * d * s4.y + h4.y, 0.f) * d;
    float oz = fmaxf(az * d * s4.z + h4.z, 0.f) * d;
    float ow = fmaxf(aw * d * s4.w + h4.w, 0.f) * d;
    __half2 h01 = __floats2half2_rn(ox, oy);
    __half2 h23 = __floats2half2_rn(oz, ow);
    uint2 p;
    p.x = *(unsigned int*)&h01;
    p.y = *(unsigned int*)&h23;
    *(uint2*)&g_abuf[(size_t)w * HID + c0] = p;
}

// ---- agg layer 2: gather g_buf2 -> BN/ReLU -> fused 128->2 dot -> g_small ------
__global__ void k_agg2(const float* __restrict__ W3) {
    int w = (blockIdx.x * blockDim.x + threadIdx.x) >> 5;
    int lane = threadIdx.x & 31;
    int c0 = lane * 4;
    if (w >= NN) return;
    float ax, ay, az, aw;
    agg_gather(g_buf2, w, c0, ax, ay, az, aw);
    float d = g_dinv[w];
    float4 s4 = *(const float4*)&g_sc2[c0];
    float4 h4 = *(const float4*)&g_sh2[c0];
    float hx = fmaxf(ax * d * s4.x + h4.x, 0.f);
    float hy = fmaxf(ay * d * s4.y + h4.y, 0.f);
    float hz = fmaxf(az * d * s4.z + h4.z, 0.f);
    float hw = fmaxf(aw * d * s4.w + h4.w, 0.f);
    float4 w01 = *(const float4*)&W3[c0 * 2];
    float4 w23 = *(const float4*)&W3[c0 * 2 + 4];
    float p0 = hx * w01.x + hy * w01.z + hz * w23.x + hw * w23.z;
    float p1 = hx * w01.y + hy * w01.w + hz * w23.y + hw * w23.w;
    #pragma unroll
    for (int off = 16; off > 0; off >>= 1) {
        p0 += __shfl_xor_sync(0xffffffffu, p0, off);
        p1 += __shfl_xor_sync(0xffffffffu, p1, off);
    }
    if (lane == 0) {
        g_small[w * 2 + 0] = p0 * d;
        g_small[w * 2 + 1] = p1 * d;
    }
}

__global__ void k_agg_out(const float* __restrict__ b3, float* __restrict__ O) {
    int n = blockIdx.x * blockDim.x + threadIdx.x;
    if (n >= NN) return;
    float ax = g_small[n * 2 + 0];
    float ay = g_small[n * 2 + 1];
    int beg = g_rowstart[n], end = g_rowstart[n + 1];
    for (int e = beg; e < end; e++) {
        int s = g_csr[e];
        float2 v = *(const float2*)&g_small[s * 2];
        ax += v.x;
        ay += v.y;
    }
    float d = g_dinv[n];
    O[n * 2 + 0] = ax * d + b3[0];
    O[n * 2 + 1] = ay * d + b3[1];
}

// ---- static init: materialize globals, smem attrs, side stream + events --------
namespace {
cudaStream_t s_side = nullptr;
cudaEvent_t  s_ev_fork = nullptr, s_ev_det = nullptr, s_ev_fork2 = nullptr,
             s_ev_join = nullptr, s_ev_a = nullptr, s_ev_b = nullptr;
struct ModulePreload {
    ModulePreload() {
        void* p = nullptr;
        cudaGetSymbolAddress(&p, g_bufH);
        cudaFuncSetAttribute((const void*)k_gemm_tc<0>,
                             cudaFuncAttributeMaxDynamicSharedMemorySize, GEMM_SMEM);
        cudaFuncSetAttribute((const void*)k_gemm_tc<1>,
                             cudaFuncAttributeMaxDynamicSharedMemorySize, GEMM_SMEM);
        cudaStreamCreateWithFlags(&s_side, cudaStreamNonBlocking);
        cudaEventCreateWithFlags(&s_ev_fork, cudaEventDisableTiming);
        cudaEventCreateWithFlags(&s_ev_det, cudaEventDisableTiming);
        cudaEventCreateWithFlags(&s_ev_fork2, cudaEventDisableTiming);
        cudaEventCreateWithFlags(&s_ev_join, cudaEventDisableTiming);
        cudaEventCreateWithFlags(&s_ev_a, cudaEventDisableTiming);
        cudaEventCreateWithFlags(&s_ev_b, cudaEventDisableTiming);
    }
};
static ModulePreload s_module_preload;
}

// ---------------- launch ----------------
extern "C" void kernel_launch(void* const* d_in, const int* in_sizes, int n_in,
                              void* d_out, int out_size) {
    const float* x   = (const float*)d_in[0];
    const void*  ei  = d_in[1];
    const float* W1  = (const float*)d_in[2];
    const float* b1  = (const float*)d_in[3];
    const float* ga1 = (const float*)d_in[4];
    const float* be1 = (const float*)d_in[5];
    const float* rm1 = (const float*)d_in[6];
    const float* rv1 = (const float*)d_in[7];
    const float* W2  = (const float*)d_in[8];
    const float* b2  = (const float*)d_in[9];
    const float* ga2 = (const float*)d_in[10];
    const float* be2 = (const float*)d_in[11];
    const float* rm2 = (const float*)d_in[12];
    const float* rv2 = (const float*)d_in[13];
    const float* W3  = (const float*)d_in[14];
    const float* b3  = (const float*)d_in[15];
    float* out = (float*)d_out;

    const int TPB = 256;
    int gridN    = (NN + TPB - 1) / TPB;
    int gridE    = (EE + TPB - 1) / TPB;
    int gridTCh  = NH / 128;                        // 391 (half of 782 tiles)
    int gridA1lo = NH / (TPB / 32);                 // 6256 blocks (8 warps each)
    int gridA1hi = (NN_PAD - NH) / (TPB / 32);      // 6256 blocks
    int gridAgg2 = (NN + (TPB / 32) - 1) / (TPB / 32);

    // fork detect onto side stream; main does weights prep + zero
    cudaEventRecord(s_ev_fork, 0);
    cudaStreamWaitEvent(s_side, s_ev_fork, 0);
    k_detect<<<1, 32, 0, s_side>>>(ei);
    cudaEventRecord(s_ev_det, s_side);

    k_bnparams<<<1, 128>>>(b1, ga1, be1, rm1, rv1, b2, ga2, be2, rm2, rv2);
    k_cvt_w<<<(2 * HID * HID + TPB - 1) / TPB, TPB>>>(W1, W2);
    k_zero<<<gridN, TPB>>>();
    cudaStreamWaitEvent(0, s_ev_det, 0);
    k_count<<<gridE, TPB>>>(ei);
    k_scan1<<<SCAN_NB, SCAN_B>>>();          // produces g_dinv + block sums

    // fork CSR tail (scan2/scan3/fill) to side; main runs GEMM1
    cudaEventRecord(s_ev_fork2, 0);
    cudaStreamWaitEvent(s_side, s_ev_fork2, 0);
    k_scan2<<<1, 128, 0, s_side>>>();
    k_scan3<<<SCAN_NB, SCAN_B, 0, s_side>>>();
    k_fill<<<gridE, TPB, 0, s_side>>>(ei);
    cudaEventRecord(s_ev_join, s_side);

    k_gemm_tc<0><<<2 * gridTCh, TPB, GEMM_SMEM>>>(x, 0);

    // join: aggregation needs CSR
    cudaStreamWaitEvent(0, s_ev_join, 0);

    // pipelined agg1 / gemm2 halves (no aliasing: gemm2 writes g_buf2,
    // agg1 reads g_bufH and writes g_abuf):
    // main: agg1_lo -> gemm2_lo ; side: agg1_hi (concurrent with gemm2_lo)
    k_agg1<<<gridA1lo, TPB>>>(0, NH);
    cudaEventRecord(s_ev_a, 0);
    cudaStreamWaitEvent(s_side, s_ev_a, 0);
    k_agg1<<<gridA1hi, TPB, 0, s_side>>>(NH, NN_PAD - NH);
    cudaEventRecord(s_ev_b, s_side);

    k_gemm_tc<1><<<gridTCh, TPB, GEMM_SMEM>>>(nullptr, 0);
    cudaStreamWaitEvent(0, s_ev_b, 0);
    k_gemm_tc<1><<<gridTCh, TPB, GEMM_SMEM>>>(nullptr, gridTCh);

    k_agg2<<<gridAgg2, TPB>>>(W3);
    k_agg_out<<<gridN, TPB>>>(b3, out);
}

// round 12
// speedup vs baseline: 1.0379x; 1.0379x over previous
#include <cuda_runtime.h>
#include <cuda_fp16.h>
#include <mma.h>

using namespace nvcuda;

#define NN 100000
#define NN_PAD 100096                     // 782 * 128
#define EE 1600000
#define HID 128
#define NC 2
#define BN_EPS 1e-5f
#define SCAN_B 1024
#define SCAN_NB ((NN + SCAN_B - 1) / SCAN_B)   // 98
#define LDS 136                                 // smem leading dim (half)
#define GEMM_SMEM (2 * 128 * LDS * (int)sizeof(__half))   // 69632 B

// ---------------- scratch (device globals; no allocation allowed) ----------------
__device__ __half g_bufH[(size_t)NN * HID];     // GEMM output = agg input, fp16
__device__ __half g_abuf[(size_t)NN_PAD * HID]; // agg1 output (h * dinv) = GEMM2 A
__device__ __half g_w1h[HID * HID];
__device__ __half g_w2h[HID * HID];
__device__ float  g_small[NN * NC];             // fused layer-3 row results
__device__ int    g_deg[NN];
__device__ float  g_dinv[NN];
__device__ int    g_rowstart[NN + 1];
__device__ int    g_blocksum[SCAN_NB];
__device__ int    g_blockoff[SCAN_NB];
__device__ int    g_fill[NN];
__device__ int    g_csr[EE];
__device__ float  g_sc1[HID], g_sh1[HID], g_sc2[HID], g_sh2[HID];
__device__ int    g_is64;

// ---------------- edge dtype detection (parallel) ----------------
__global__ void k_detect(const void* __restrict__ ei) {
    int tid = threadIdx.x;   // 32 threads
    const long long* p = (const long long*)ei;
    int bad = 0;
    #pragma unroll
    for (int k = 0; k < 2; k++) {
        long long v = p[(tid * 2 + k) * 997];
        bad |= (v < 0 || v >= NN) ? 1 : 0;
    }
    unsigned m = __ballot_sync(0xffffffffu, bad);
    if (tid == 0) g_is64 = (m == 0) ? 1 : 0;
}

__device__ __forceinline__ int edge_at(const void* ei, size_t idx) {
    if (g_is64) return (int)((const long long*)ei)[idx];
    return ((const int*)ei)[idx];
}

// ---------------- CSR build ----------------
__global__ void k_zero() {
    int i = blockIdx.x * blockDim.x + threadIdx.x;
    if (i < NN) { g_deg[i] = 0; g_fill[i] = 0; }
}

__global__ void k_count(const void* __restrict__ ei) {
    int e = blockIdx.x * blockDim.x + threadIdx.x;
    if (e < EE) atomicAdd(&g_deg[edge_at(ei, (size_t)EE + e)], 1);
}

__global__ void k_scan1() {
    __shared__ int warpsum[32];
    int tid = threadIdx.x;
    int i = blockIdx.x * SCAN_B + tid;
    int v = (i < NN) ? g_deg[i] : 0;
    if (i < NN) g_dinv[i] = rsqrtf((float)(v + 1));   // +1 self-loop
    int lane = tid & 31, warp = tid >> 5;
    int s = v;
    #pragma unroll
    for (int off = 1; off < 32; off <<= 1) {
        int t = __shfl_up_sync(0xffffffffu, s, off);
        if (lane >= off) s += t;
    }
    if (lane == 31) warpsum[warp] = s;
    __syncthreads();
    if (warp == 0) {
        int ws = (lane < SCAN_B / 32) ? warpsum[lane] : 0;
        #pragma unroll
        for (int off = 1; off < 32; off <<= 1) {
            int t = __shfl_up_sync(0xffffffffu, ws, off);
            if (lane >= off) ws += t;
        }
        warpsum[lane] = ws;
    }
    __syncthreads();
    int base = (warp > 0) ? warpsum[warp - 1] : 0;
    if (i < NN) g_rowstart[i] = base + s - v;
    if (tid == SCAN_B - 1) g_blocksum[blockIdx.x] = base + s;
}

__global__ void k_scan2() {
    __shared__ int sh[128];
    int tid = threadIdx.x;
    int v = (tid < SCAN_NB) ? g_blocksum[tid] : 0;
    int lane = tid & 31, warp = tid >> 5;
    int s = v;
    #pragma unroll
    for (int off = 1; off < 32; off <<= 1) {
        int t = __shfl_up_sync(0xffffffffu, s, off);
        if (lane >= off) s += t;
    }
    if (lane == 31) sh[warp] = s;
    __syncthreads();
    if (warp == 0 && lane < 4) {
        int ws = sh[lane];
        #pragma unroll
        for (int off = 1; off < 4; off <<= 1) {
            int t = __shfl_up_sync(0x0000000fu, ws, off);
            if (lane >= off) ws += t;
        }
        sh[lane] = ws;
    }
    __syncthreads();
    int base = (warp > 0) ? sh[warp - 1] : 0;
    if (tid < SCAN_NB) g_blockoff[tid] = base + s - v;
    if (tid == 127) g_rowstart[NN] = base + s;
}

__global__ void k_scan3() {
    int i = blockIdx.x * SCAN_B + threadIdx.x;
    if (i < NN) g_rowstart[i] += g_blockoff[blockIdx.x];
}

__global__ void k_fill(const void* __restrict__ ei) {
    int e = blockIdx.x * blockDim.x + threadIdx.x;
    if (e < EE) {
        int d = edge_at(ei, (size_t)EE + e);
        int s = edge_at(ei, e);
        int p = atomicAdd(&g_fill[d], 1);
        g_csr[g_rowstart[d] + p] = s;
    }
}

// ---------------- BN parameter folding ----------------
__global__ void k_bnparams(const float* __restrict__ b1, const float* __restrict__ ga1,
                           const float* __restrict__ be1, const float* __restrict__ rm1,
                           const float* __restrict__ rv1,
                           const float* __restrict__ b2, const float* __restrict__ ga2,
                           const float* __restrict__ be2, const float* __restrict__ rm2,
                           const float* __restrict__ rv2) {
    int c = threadIdx.x;
    if (c < HID) {
        float s1 = ga1[c] * rsqrtf(rv1[c] + BN_EPS);
        g_sc1[c] = s1;
        g_sh1[c] = (b1[c] - rm1[c]) * s1 + be1[c];
        float s2 = ga2[c] * rsqrtf(rv2[c] + BN_EPS);
        g_sc2[c] = s2;
        g_sh2[c] = (b2[c] - rm2[c]) * s2 + be2[c];
    }
}

__global__ void k_cvt_w(const float* __restrict__ W1, const float* __restrict__ W2) {
    int i = blockIdx.x * blockDim.x + threadIdx.x;
    if (i < HID * HID) g_w1h[i] = __float2half(W1[i]);
    else if (i < 2 * HID * HID) g_w2h[i - HID * HID] = __float2half(W2[i - HID * HID]);
}

// ---------------- tensor-core GEMM, smem-staged 128x128 tile --------------------
// SRC=0: A = x (fp32, scaled by dinv during staging), W = g_w1h
// SRC=1: A = g_abuf (fp16, already scaled),           W = g_w2h
template <int SRC>
__global__ void k_gemm_tc(const float* __restrict__ X) {
    extern __shared__ __half smem[];
    __half* sA = smem;                 // [128][LDS]
    __half* sW = smem + 128 * LDS;     // [128][LDS]
    __shared__ __align__(16) float scratch[8][16][20];

    int tid = threadIdx.x;
    int row0 = blockIdx.x * 128;

    {
        const __half* __restrict__ Wh = (SRC == 0) ? g_w1h : g_w2h;
        for (int i = tid; i < 128 * 16; i += 256) {
            int r = i >> 4, q = i & 15;
            uint4 v = *(const uint4*)&Wh[r * HID + q * 8];
            *(uint4*)&sW[r * LDS + q * 8] = v;
        }
    }
    if (SRC == 0) {
        for (int i = tid; i < 128 * 32; i += 256) {
            int r = i >> 5, q = i & 31;
            int gr = row0 + r;
            __half2 h01, h23;
            if (gr < NN) {
                float4 v = *(const float4*)&X[(size_t)gr * HID + q * 4];
                float d = g_dinv[gr];
                h01 = __floats2half2_rn(v.x * d, v.y * d);
                h23 = __floats2half2_rn(v.z * d, v.w * d);
            } else {
                h01 = __floats2half2_rn(0.f, 0.f);
                h23 = h01;
            }
            uint2 p;
            p.x = *(unsigned int*)&h01;
            p.y = *(unsigned int*)&h23;
            *(uint2*)&sA[r * LDS + q * 4] = p;
        }
    } else {
        for (int i = tid; i < 128 * 16; i += 256) {
            int r = i >> 4, q = i & 15;
            int gr = row0 + r;     // g_abuf padded to NN_PAD with zeros
            uint4 v = *(const uint4*)&g_abuf[(size_t)gr * HID + q * 8];
            *(uint4*)&sA[r * LDS + q * 8] = v;
        }
    }
    __syncthreads();

    int warp = tid >> 5, lane = tid & 31;
    int rg = warp >> 1, cg = warp & 1;
    int wr0 = rg * 32, col0 = cg * 64;

    wmma::fragment<wmma::accumulator, 16, 16, 16, float> c[2][4];
    #pragma unroll
    for (int i = 0; i < 2; i++)
        #pragma unroll
        for (int j = 0; j < 4; j++) wmma::fill_fragment(c[i][j], 0.f);

    #pragma unroll
    for (int k = 0; k < HID; k += 16) {
        wmma::fragment<wmma::matrix_a, 16, 16, 16, __half, wmma::row_major> a[2];
        wmma::fragment<wmma::matrix_b, 16, 16, 16, __half, wmma::row_major> b[4];
        wmma::load_matrix_sync(a[0], sA + (wr0 + 0) * LDS + k, LDS);
        wmma::load_matrix_sync(a[1], sA + (wr0 + 16) * LDS + k, LDS);
        #pragma unroll
        for (int j = 0; j < 4; j++)
            wmma::load_matrix_sync(b[j], sW + k * LDS + col0 + j * 16, LDS);
        #pragma unroll
        for (int i = 0; i < 2; i++)
            #pragma unroll
            for (int j = 0; j < 4; j++)
                wmma::mma_sync(c[i][j], a[i], b[j], c[i][j]);
    }

    #pragma unroll
    for (int i = 0; i < 2; i++) {
        #pragma unroll
        for (int j = 0; j < 4; j++) {
            wmma::store_matrix_sync(&scratch[warp][0][0], c[i][j], 20, wmma::mem_row_major);
            __syncwarp();
            int r = lane >> 1, ch = lane & 1;
            int gr = row0 + wr0 + i * 16 + r;
            if (gr < NN) {
                int gc = col0 + j * 16 + ch * 8;
                const float* s = &scratch[warp][r][ch * 8];
                __half2 h0 = __floats2half2_rn(s[0], s[1]);
                __half2 h1 = __floats2half2_rn(s[2], s[3]);
                __half2 h2 = __floats2half2_rn(s[4], s[5]);
                __half2 h3 = __floats2half2_rn(s[6], s[7]);
                uint4 p;
                p.x = *(unsigned int*)&h0;
                p.y = *(unsigned int*)&h1;
                p.z = *(unsigned int*)&h2;
                p.w = *(unsigned int*)&h3;
                *(uint4*)&g_bufH[(size_t)gr * HID + gc] = p;
            }
            __syncwarp();
        }
    }
}

// ------------- shared gather body (warp per node, uint2, 4-wide unroll) ---------
__device__ __forceinline__ void agg_gather(int w, int c0, float& ax, float& ay,
                                           float& az, float& aw) {
    int beg = g_rowstart[w], end = g_rowstart[w + 1];
    {
        uint2 p = *(const uint2*)&g_bufH[(size_t)w * HID + c0];
        float2 f01 = __half22float2(*(__half2*)&p.x);
        float2 f23 = __half22float2(*(__half2*)&p.y);
        ax = f01.x; ay = f01.y; az = f23.x; aw = f23.y;
    }
    int e = beg;
    for (; e + 4 <= end; e += 4) {
        int s0 = g_csr[e];
        int s1 = g_csr[e + 1];
        int s2 = g_csr[e + 2];
        int s3 = g_csr[e + 3];
        uint2 p0 = *(const uint2*)&g_bufH[(size_t)s0 * HID + c0];
        uint2 p1 = *(const uint2*)&g_bufH[(size_t)s1 * HID + c0];
        uint2 p2 = *(const uint2*)&g_bufH[(size_t)s2 * HID + c0];
        uint2 p3 = *(const uint2*)&g_bufH[(size_t)s3 * HID + c0];
        float2 a01 = __half22float2(*(__half2*)&p0.x);
        float2 a23 = __half22float2(*(__half2*)&p0.y);
        float2 b01 = __half22float2(*(__half2*)&p1.x);
        float2 b23 = __half22float2(*(__half2*)&p1.y);
        float2 c01 = __half22float2(*(__half2*)&p2.x);
        float2 c23 = __half22float2(*(__half2*)&p2.y);
        float2 d01 = __half22float2(*(__half2*)&p3.x);
        float2 d23 = __half22float2(*(__half2*)&p3.y);
        ax += (a01.x + b01.x) + (c01.x + d01.x);
        ay += (a01.y + b01.y) + (c01.y + d01.y);
        az += (a23.x + b23.x) + (c23.x + d23.x);
        aw += (a23.y + b23.y) + (c23.y + d23.y);
    }
    for (; e < end; e++) {
        int s0 = g_csr[e];
        uint2 p0 = *(const uint2*)&g_bufH[(size_t)s0 * HID + c0];
        float2 a01 = __half22float2(*(__half2*)&p0.x);
        float2 a23 = __half22float2(*(__half2*)&p0.y);
        ax += a01.x; ay += a01.y; az += a23.x; aw += a23.y;
    }
}

// ---------------- agg layer 1: gather -> BN/ReLU -> *dinv -> g_abuf -------------
__global__ void k_agg1() {
    int w = (blockIdx.x * blockDim.x + threadIdx.x) >> 5;
    int lane = threadIdx.x & 31;
    int c0 = lane * 4;
    if (w >= NN) {
        if (w < NN_PAD) {
            uint2 p;
            p.x = 0u; p.y = 0u;
            *(uint2*)&g_abuf[(size_t)w * HID + c0] = p;
        }
        return;
    }
    float ax, ay, az, aw;
    agg_gather(w, c0, ax, ay, az, aw);
    float d = g_dinv[w];
    float4 s4 = *(const float4*)&g_sc1[c0];
    float4 h4 = *(const float4*)&g_sh1[c0];
    float ox = fmaxf(ax * d * s4.x + h4.x, 0.f) * d;
    float oy = fmaxf(ay * d * s4.y + h4.y, 0.f) * d;
    float oz = fmaxf(az * d * s4.z + h4.z, 0.f) * d;
    float ow = fmaxf(aw * d * s4.w + h4.w, 0.f) * d;
    __half2 h01 = __floats2half2_rn(ox, oy);
    __half2 h23 = __floats2half2_rn(oz, ow);
    uint2 p;
    p.x = *(unsigned int*)&h01;
    p.y = *(unsigned int*)&h23;
    *(uint2*)&g_abuf[(size_t)w * HID + c0] = p;
}

// ---- agg layer 2: gather -> BN/ReLU -> fused 128->2 dot with W3 -> g_small -----
__global__ void k_agg2(const float* __restrict__ W3) {
    int w = (blockIdx.x * blockDim.x + threadIdx.x) >> 5;
    int lane = threadIdx.x & 31;
    int c0 = lane * 4;
    if (w >= NN) return;
    float ax, ay, az, aw;
    agg_gather(w, c0, ax, ay, az, aw);
    float d = g_dinv[w];
    float4 s4 = *(const float4*)&g_sc2[c0];
    float4 h4 = *(const float4*)&g_sh2[c0];
    float hx = fmaxf(ax * d * s4.x + h4.x, 0.f);
    float hy = fmaxf(ay * d * s4.y + h4.y, 0.f);
    float hz = fmaxf(az * d * s4.z + h4.z, 0.f);
    float hw = fmaxf(aw * d * s4.w + h4.w, 0.f);
    float4 w01 = *(const float4*)&W3[c0 * 2];
    float4 w23 = *(const float4*)&W3[c0 * 2 + 4];
    float p0 = hx * w01.x + hy * w01.z + hz * w23.x + hw * w23.z;
    float p1 = hx * w01.y + hy * w01.w + hz * w23.y + hw * w23.w;
    #pragma unroll
    for (int off = 16; off > 0; off >>= 1) {
        p0 += __shfl_xor_sync(0xffffffffu, p0, off);
        p1 += __shfl_xor_sync(0xffffffffu, p1, off);
    }
    if (lane == 0) {
        g_small[w * 2 + 0] = p0 * d;
        g_small[w * 2 + 1] = p1 * d;
    }
}

__global__ void k_agg_out(const float* __restrict__ b3, float* __restrict__ O) {
    int n = blockIdx.x * blockDim.x + threadIdx.x;
    if (n >= NN) return;
    float ax = g_small[n * 2 + 0];
    float ay = g_small[n * 2 + 1];
    int beg = g_rowstart[n], end = g_rowstart[n + 1];
    for (int e = beg; e < end; e++) {
        int s = g_csr[e];
        float2 v = *(const float2*)&g_small[s * 2];
        ax += v.x;
        ay += v.y;
    }
    float d = g_dinv[n];
    O[n * 2 + 0] = ax * d + b3[0];
    O[n * 2 + 1] = ay * d + b3[1];
}

// ---- static init: materialize globals, smem attrs, side stream + events --------
namespace {
cudaStream_t s_side = nullptr;
cudaEvent_t  s_ev_fork = nullptr, s_ev_det = nullptr, s_ev_fork2 = nullptr,
             s_ev_join = nullptr;
struct ModulePreload {
    ModulePreload() {
        void* p = nullptr;
        cudaGetSymbolAddress(&p, g_bufH);
        cudaFuncSetAttribute((const void*)k_gemm_tc<0>,
                             cudaFuncAttributeMaxDynamicSharedMemorySize, GEMM_SMEM);
        cudaFuncSetAttribute((const void*)k_gemm_tc<1>,
                             cudaFuncAttributeMaxDynamicSharedMemorySize, GEMM_SMEM);
        cudaStreamCreateWithFlags(&s_side, cudaStreamNonBlocking);
        cudaEventCreateWithFlags(&s_ev_fork, cudaEventDisableTiming);
        cudaEventCreateWithFlags(&s_ev_det, cudaEventDisableTiming);
        cudaEventCreateWithFlags(&s_ev_fork2, cudaEventDisableTiming);
        cudaEventCreateWithFlags(&s_ev_join, cudaEventDisableTiming);
    }
};
static ModulePreload s_module_preload;
}

// ---------------- launch ----------------
extern "C" void kernel_launch(void* const* d_in, const int* in_sizes, int n_in,
                              void* d_out, int out_size) {
    const float* x   = (const float*)d_in[0];
    const void*  ei  = d_in[1];
    const float* W1  = (const float*)d_in[2];
    const float* b1  = (const float*)d_in[3];
    const float* ga1 = (const float*)d_in[4];
    const float* be1 = (const float*)d_in[5];
    const float* rm1 = (const float*)d_in[6];
    const float* rv1 = (const float*)d_in[7];
    const float* W2  = (const float*)d_in[8];
    const float* b2  = (const float*)d_in[9];
    const float* ga2 = (const float*)d_in[10];
    const float* be2 = (const float*)d_in[11];
    const float* rm2 = (const float*)d_in[12];
    const float* rv2 = (const float*)d_in[13];
    const float* W3  = (const float*)d_in[14];
    const float* b3  = (const float*)d_in[15];
    float* out = (float*)d_out;

    const int TPB = 256;
    int gridN    = (NN + TPB - 1) / TPB;
    int gridE    = (EE + TPB - 1) / TPB;
    int gridTC   = NN_PAD / 128;                          // 782
    int gridAgg1 = (NN_PAD + (TPB / 32) - 1) / (TPB / 32);
    int gridAgg2 = (NN + (TPB / 32) - 1) / (TPB / 32);

    // fork detect onto side stream; main does weights prep + zero
    cudaEventRecord(s_ev_fork, 0);
    cudaStreamWaitEvent(s_side, s_ev_fork, 0);
    k_detect<<<1, 32, 0, s_side>>>(ei);
    cudaEventRecord(s_ev_det, s_side);

    k_bnparams<<<1, 128>>>(b1, ga1, be1, rm1, rv1, b2, ga2, be2, rm2, rv2);
    k_cvt_w<<<(2 * HID * HID + TPB - 1) / TPB, TPB>>>(W1, W2);
    k_zero<<<gridN, TPB>>>();
    cudaStreamWaitEvent(0, s_ev_det, 0);
    k_count<<<gridE, TPB>>>(ei);
    k_scan1<<<SCAN_NB, SCAN_B>>>();          // produces g_dinv + block sums

    // fork CSR tail (scan2/scan3/fill) to side; main runs GEMM1
    cudaEventRecord(s_ev_fork2, 0);
    cudaStreamWaitEvent(s_side, s_ev_fork2, 0);
    k_scan2<<<1, 128, 0, s_side>>>();
    k_scan3<<<SCAN_NB, SCAN_B, 0, s_side>>>();
    k_fill<<<gridE, TPB, 0, s_side>>>(ei);
    cudaEventRecord(s_ev_join, s_side);

    // main: GEMM1 needs only g_dinv + g_w1h
    k_gemm_tc<0><<<gridTC, TPB, GEMM_SMEM>>>(x);

    // join before aggregation (needs CSR)
    cudaStreamWaitEvent(0, s_ev_join, 0);

    k_agg1<<<gridAgg1, TPB>>>();
    k_gemm_tc<1><<<gridTC, TPB, GEMM_SMEM>>>(nullptr);
    k_agg2<<<gridAgg2, TPB>>>(W3);
    k_agg_out<<<gridN, TPB>>>(b3, out);
}

// round 15
// speedup vs baseline: 1.0479x; 1.0097x over previous
#include <cuda_runtime.h>
#include <cuda_fp16.h>
#include <mma.h>

using namespace nvcuda;

#define NN 100000
#define NN_PAD 100096                     // 782 * 128
#define EE 1600000
#define HID 128
#define NC 2
#define BN_EPS 1e-5f
#define SCAN_B 1024
#define SCAN_NB ((NN + SCAN_B - 1) / SCAN_B)   // 98
#define LDS 136                                 // smem leading dim (half)
#define GEMM_SMEM (2 * 128 * LDS * (int)sizeof(__half))   // 69632 B

// ---------------- scratch (device globals; no allocation allowed) ----------------
__device__ __half g_bufH[(size_t)NN * HID];     // GEMM output = agg input, fp16
__device__ __half g_abuf[(size_t)NN_PAD * HID]; // agg1 output (h * dinv) = GEMM2 A
__device__ __half g_w1h[HID * HID];
__device__ __half g_w2h[HID * HID];
__device__ float  g_small[NN * NC];             // fused layer-3 row results
__device__ int    g_deg[NN];
__device__ float  g_dinv[NN];
__device__ int    g_rowstart[NN + 1];
__device__ int    g_blocksum[SCAN_NB];
__device__ int    g_blockoff[SCAN_NB];
__device__ int    g_fill[NN];
__device__ int    g_csr[EE];
__device__ float  g_sc1[HID], g_sh1[HID], g_sc2[HID], g_sh2[HID];
__device__ int    g_is64;

// ---------------- edge dtype detection (parallel) ----------------
__global__ void k_detect(const void* __restrict__ ei) {
    int tid = threadIdx.x;   // 32 threads
    const long long* p = (const long long*)ei;
    int bad = 0;
    #pragma unroll
    for (int k = 0; k < 2; k++) {
        long long v = p[(tid * 2 + k) * 997];
        bad |= (v < 0 || v >= NN) ? 1 : 0;
    }
    unsigned m = __ballot_sync(0xffffffffu, bad);
    if (tid == 0) g_is64 = (m == 0) ? 1 : 0;
}

__device__ __forceinline__ int edge_at(const void* ei, size_t idx) {
    if (g_is64) return (int)((const long long*)ei)[idx];
    return ((const int*)ei)[idx];
}

// ---------------- CSR build ----------------
__global__ void k_zero() {
    int i = blockIdx.x * blockDim.x + threadIdx.x;
    if (i < NN) { g_deg[i] = 0; g_fill[i] = 0; }
}

__global__ void k_count(const void* __restrict__ ei) {
    int e = blockIdx.x * blockDim.x + threadIdx.x;
    if (e < EE) atomicAdd(&g_deg[edge_at(ei, (size_t)EE + e)], 1);
}

__global__ void k_scan1() {
    __shared__ int warpsum[32];
    int tid = threadIdx.x;
    int i = blockIdx.x * SCAN_B + tid;
    int v = (i < NN) ? g_deg[i] : 0;
    if (i < NN) g_dinv[i] = rsqrtf((float)(v + 1));   // +1 self-loop
    int lane = tid & 31, warp = tid >> 5;
    int s = v;
    #pragma unroll
    for (int off = 1; off < 32; off <<= 1) {
        int t = __shfl_up_sync(0xffffffffu, s, off);
        if (lane >= off) s += t;
    }
    if (lane == 31) warpsum[warp] = s;
    __syncthreads();
    if (warp == 0) {
        int ws = (lane < SCAN_B / 32) ? warpsum[lane] : 0;
        #pragma unroll
        for (int off = 1; off < 32; off <<= 1) {
            int t = __shfl_up_sync(0xffffffffu, ws, off);
            if (lane >= off) ws += t;
        }
        warpsum[lane] = ws;
    }
    __syncthreads();
    int base = (warp > 0) ? warpsum[warp - 1] : 0;
    if (i < NN) g_rowstart[i] = base + s - v;
    if (tid == SCAN_B - 1) g_blocksum[blockIdx.x] = base + s;
}

__global__ void k_scan2() {
    __shared__ int sh[128];
    int tid = threadIdx.x;
    int v = (tid < SCAN_NB) ? g_blocksum[tid] : 0;
    int lane = tid & 31, warp = tid >> 5;
    int s = v;
    #pragma unroll
    for (int off = 1; off < 32; off <<= 1) {
        int t = __shfl_up_sync(0xffffffffu, s, off);
        if (lane >= off) s += t;
    }
    if (lane == 31) sh[warp] = s;
    __syncthreads();
    if (warp == 0 && lane < 4) {
        int ws = sh[lane];
        #pragma unroll
        for (int off = 1; off < 4; off <<= 1) {
            int t = __shfl_up_sync(0x0000000fu, ws, off);
            if (lane >= off) ws += t;
        }
        sh[lane] = ws;
    }
    __syncthreads();
    int base = (warp > 0) ? sh[warp - 1] : 0;
    if (tid < SCAN_NB) g_blockoff[tid] = base + s - v;
    if (tid == 127) g_rowstart[NN] = base + s;
}

__global__ void k_scan3() {
    int i = blockIdx.x * SCAN_B + threadIdx.x;
    if (i < NN) g_rowstart[i] += g_blockoff[blockIdx.x];
}

__global__ void k_fill(const void* __restrict__ ei) {
    int e = blockIdx.x * blockDim.x + threadIdx.x;
    if (e < EE) {
        int d = edge_at(ei, (size_t)EE + e);
        int s = edge_at(ei, e);
        int p = atomicAdd(&g_fill[d], 1);
        g_csr[g_rowstart[d] + p] = s;
    }
}

// ---------------- BN parameter folding ----------------
__global__ void k_bnparams(const float* __restrict__ b1, const float* __restrict__ ga1,
                           const float* __restrict__ be1, const float* __restrict__ rm1,
                           const float* __restrict__ rv1,
                           const float* __restrict__ b2, const float* __restrict__ ga2,
                           const float* __restrict__ be2, const float* __restrict__ rm2,
                           const float* __restrict__ rv2) {
    int c = threadIdx.x;
    if (c < HID) {
        float s1 = ga1[c] * rsqrtf(rv1[c] + BN_EPS);
        g_sc1[c] = s1;
        g_sh1[c] = (b1[c] - rm1[c]) * s1 + be1[c];
        float s2 = ga2[c] * rsqrtf(rv2[c] + BN_EPS);
        g_sc2[c] = s2;
        g_sh2[c] = (b2[c] - rm2[c]) * s2 + be2[c];
    }
}

__global__ void k_cvt_w(const float* __restrict__ W1, const float* __restrict__ W2) {
    int i = blockIdx.x * blockDim.x + threadIdx.x;
    if (i < HID * HID) g_w1h[i] = __float2half(W1[i]);
    else if (i < 2 * HID * HID) g_w2h[i - HID * HID] = __float2half(W2[i - HID * HID]);
}

// ---------------- tensor-core GEMM, smem-staged 128x128 tile --------------------
// SRC=0: A = x (fp32, scaled by dinv during staging), W = g_w1h
// SRC=1: A = g_abuf (fp16, already scaled),           W = g_w2h
template <int SRC>
__global__ void k_gemm_tc(const float* __restrict__ X) {
    extern __shared__ __half smem[];
    __half* sA = smem;                 // [128][LDS]
    __half* sW = smem + 128 * LDS;     // [128][LDS]
    __shared__ __align__(16) float scratch[8][16][20];

    int tid = threadIdx.x;
    int row0 = blockIdx.x * 128;

    {
        const __half* __restrict__ Wh = (SRC == 0) ? g_w1h : g_w2h;
        for (int i = tid; i < 128 * 16; i += 256) {
            int r = i >> 4, q = i & 15;
            uint4 v = *(const uint4*)&Wh[r * HID + q * 8];
            *(uint4*)&sW[r * LDS + q * 8] = v;
        }
    }
    if (SRC == 0) {
        for (int i = tid; i < 128 * 32; i += 256) {
            int r = i >> 5, q = i & 31;
            int gr = row0 + r;
            __half2 h01, h23;
            if (gr < NN) {
                float4 v = *(const float4*)&X[(size_t)gr * HID + q * 4];
                float d = g_dinv[gr];
                h01 = __floats2half2_rn(v.x * d, v.y * d);
                h23 = __floats2half2_rn(v.z * d, v.w * d);
            } else {
                h01 = __floats2half2_rn(0.f, 0.f);
                h23 = h01;
            }
            uint2 p;
            p.x = *(unsigned int*)&h01;
            p.y = *(unsigned int*)&h23;
            *(uint2*)&sA[r * LDS + q * 4] = p;
        }
    } else {
        for (int i = tid; i < 128 * 16; i += 256) {
            int r = i >> 4, q = i & 15;
            int gr = row0 + r;     // g_abuf padded to NN_PAD with zeros
            uint4 v = *(const uint4*)&g_abuf[(size_t)gr * HID + q * 8];
            *(uint4*)&sA[r * LDS + q * 8] = v;
        }
    }
    __syncthreads();

    int warp = tid >> 5, lane = tid & 31;
    int rg = warp >> 1, cg = warp & 1;
    int wr0 = rg * 32, col0 = cg * 64;

    wmma::fragment<wmma::accumulator, 16, 16, 16, float> c[2][4];
    #pragma unroll
    for (int i = 0; i < 2; i++)
        #pragma unroll
        for (int j = 0; j < 4; j++) wmma::fill_fragment(c[i][j], 0.f);

    #pragma unroll
    for (int k = 0; k < HID; k += 16) {
        wmma::fragment<wmma::matrix_a, 16, 16, 16, __half, wmma::row_major> a[2];
        wmma::fragment<wmma::matrix_b, 16, 16, 16, __half, wmma::row_major> b[4];
        wmma::load_matrix_sync(a[0], sA + (wr0 + 0) * LDS + k, LDS);
        wmma::load_matrix_sync(a[1], sA + (wr0 + 16) * LDS + k, LDS);
        #pragma unroll
        for (int j = 0; j < 4; j++)
            wmma::load_matrix_sync(b[j], sW + k * LDS + col0 + j * 16, LDS);
        #pragma unroll
        for (int i = 0; i < 2; i++)
            #pragma unroll
            for (int j = 0; j < 4; j++)
                wmma::mma_sync(c[i][j], a[i], b[j], c[i][j]);
    }

    #pragma unroll
    for (int i = 0; i < 2; i++) {
        #pragma unroll
        for (int j = 0; j < 4; j++) {
            wmma::store_matrix_sync(&scratch[warp][0][0], c[i][j], 20, wmma::mem_row_major);
            __syncwarp();
            int r = lane >> 1, ch = lane & 1;
            int gr = row0 + wr0 + i * 16 + r;
            if (gr < NN) {
                int gc = col0 + j * 16 + ch * 8;
                const float* s = &scratch[warp][r][ch * 8];
                __half2 h0 = __floats2half2_rn(s[0], s[1]);
                __half2 h1 = __floats2half2_rn(s[2], s[3]);
                __half2 h2 = __floats2half2_rn(s[4], s[5]);
                __half2 h3 = __floats2half2_rn(s[6], s[7]);
                uint4 p;
                p.x = *(unsigned int*)&h0;
                p.y = *(unsigned int*)&h1;
                p.z = *(unsigned int*)&h2;
                p.w = *(unsigned int*)&h3;
                *(uint4*)&g_bufH[(size_t)gr * HID + gc] = p;
            }
            __syncwarp();
        }
    }
}

// ---- gather body: HALF-WARP per node, uint4 (LDG.128) lanes, 2-wide unroll -----
// 16 lanes x 16B = one 256B row per half-warp; one LDG.128 serves 2 rows/warp.
__device__ __forceinline__ void agg_gather8(int w, int c0, float a[8]) {
    int beg = g_rowstart[w], end = g_rowstart[w + 1];
    {
        uint4 p = *(const uint4*)&g_bufH[(size_t)w * HID + c0];
        float2 f0 = __half22float2(*(__half2*)&p.x);
        float2 f1 = __half22float2(*(__half2*)&p.y);
        float2 f2 = __half22float2(*(__half2*)&p.z);
        float2 f3 = __half22float2(*(__half2*)&p.w);
        a[0] = f0.x; a[1] = f0.y; a[2] = f1.x; a[3] = f1.y;
        a[4] = f2.x; a[5] = f2.y; a[6] = f3.x; a[7] = f3.y;
    }
    int e = beg;
    for (; e + 2 <= end; e += 2) {
        int s0 = g_csr[e];
        int s1 = g_csr[e + 1];
        uint4 p0 = *(const uint4*)&g_bufH[(size_t)s0 * HID + c0];
        uint4 p1 = *(const uint4*)&g_bufH[(size_t)s1 * HID + c0];
        float2 f0 = __half22float2(*(__half2*)&p0.x);
        float2 f1 = __half22float2(*(__half2*)&p0.y);
        float2 f2 = __half22float2(*(__half2*)&p0.z);
        float2 f3 = __half22float2(*(__half2*)&p0.w);
        float2 g0 = __half22float2(*(__half2*)&p1.x);
        float2 g1 = __half22float2(*(__half2*)&p1.y);
        float2 g2 = __half22float2(*(__half2*)&p1.z);
        float2 g3 = __half22float2(*(__half2*)&p1.w);
        a[0] += f0.x + g0.x; a[1] += f0.y + g0.y;
        a[2] += f1.x + g1.x; a[3] += f1.y + g1.y;
        a[4] += f2.x + g2.x; a[5] += f2.y + g2.y;
        a[6] += f3.x + g3.x; a[7] += f3.y + g3.y;
    }
    if (e < end) {
        int s0 = g_csr[e];
        uint4 p0 = *(const uint4*)&g_bufH[(size_t)s0 * HID + c0];
        float2 f0 = __half22float2(*(__half2*)&p0.x);
        float2 f1 = __half22float2(*(__half2*)&p0.y);
        float2 f2 = __half22float2(*(__half2*)&p0.z);
        float2 f3 = __half22float2(*(__half2*)&p0.w);
        a[0] += f0.x; a[1] += f0.y; a[2] += f1.x; a[3] += f1.y;
        a[4] += f2.x; a[5] += f2.y; a[6] += f3.x; a[7] += f3.y;
    }
}

// ---------------- agg layer 1: gather -> BN/ReLU -> *dinv -> g_abuf -------------
__global__ void k_agg1() {
    int w = (blockIdx.x * blockDim.x + threadIdx.x) >> 4;    // half-warp per node
    int l16 = threadIdx.x & 15;
    int c0 = l16 * 8;
    if (w >= NN) {
        if (w < NN_PAD) {
            uint4 p;
            p.x = p.y = p.z = p.w = 0u;
            *(uint4*)&g_abuf[(size_t)w * HID + c0] = p;
        }
        return;
    }
    float a[8];
    agg_gather8(w, c0, a);
    float d = g_dinv[w];
    float4 s4a = *(const float4*)&g_sc1[c0];
    float4 s4b = *(const float4*)&g_sc1[c0 + 4];
    float4 h4a = *(const float4*)&g_sh1[c0];
    float4 h4b = *(const float4*)&g_sh1[c0 + 4];
    float o0 = fmaxf(a[0] * d * s4a.x + h4a.x, 0.f) * d;
    float o1 = fmaxf(a[1] * d * s4a.y + h4a.y, 0.f) * d;
    float o2 = fmaxf(a[2] * d * s4a.z + h4a.z, 0.f) * d;
    float o3 = fmaxf(a[3] * d * s4a.w + h4a.w, 0.f) * d;
    float o4 = fmaxf(a[4] * d * s4b.x + h4b.x, 0.f) * d;
    float o5 = fmaxf(a[5] * d * s4b.y + h4b.y, 0.f) * d;
    float o6 = fmaxf(a[6] * d * s4b.z + h4b.z, 0.f) * d;
    float o7 = fmaxf(a[7] * d * s4b.w + h4b.w, 0.f) * d;
    __half2 q0 = __floats2half2_rn(o0, o1);
    __half2 q1 = __floats2half2_rn(o2, o3);
    __half2 q2 = __floats2half2_rn(o4, o5);
    __half2 q3 = __floats2half2_rn(o6, o7);
    uint4 p;
    p.x = *(unsigned int*)&q0;
    p.y = *(unsigned int*)&q1;
    p.z = *(unsigned int*)&q2;
    p.w = *(unsigned int*)&q3;
    *(uint4*)&g_abuf[(size_t)w * HID + c0] = p;
}

// ---- agg layer 2: gather -> BN/ReLU -> fused 128->2 dot with W3 -> g_small -----
__global__ void k_agg2(const float* __restrict__ W3) {
    int w = (blockIdx.x * blockDim.x + threadIdx.x) >> 4;    // half-warp per node
    int l16 = threadIdx.x & 15;
    int c0 = l16 * 8;
    if (w >= NN) return;
    float a[8];
    agg_gather8(w, c0, a);
    float d = g_dinv[w];
    float4 s4a = *(const float4*)&g_sc2[c0];
    float4 s4b = *(const float4*)&g_sc2[c0 + 4];
    float4 h4a = *(const float4*)&g_sh2[c0];
    float4 h4b = *(const float4*)&g_sh2[c0 + 4];
    float h0 = fmaxf(a[0] * d * s4a.x + h4a.x, 0.f);
    float h1 = fmaxf(a[1] * d * s4a.y + h4a.y, 0.f);
    float h2 = fmaxf(a[2] * d * s4a.z + h4a.z, 0.f);
    float h3 = fmaxf(a[3] * d * s4a.w + h4a.w, 0.f);
    float h4 = fmaxf(a[4] * d * s4b.x + h4b.x, 0.f);
    float h5 = fmaxf(a[5] * d * s4b.y + h4b.y, 0.f);
    float h6 = fmaxf(a[6] * d * s4b.z + h4b.z, 0.f);
    float h7 = fmaxf(a[7] * d * s4b.w + h4b.w, 0.f);
    // W3 rows c0..c0+7, 2 cols each: 16 consecutive floats
    float4 w0 = *(const float4*)&W3[c0 * 2];
    float4 w1 = *(const float4*)&W3[c0 * 2 + 4];
    float4 w2 = *(const float4*)&W3[c0 * 2 + 8];
    float4 w3 = *(const float4*)&W3[c0 * 2 + 12];
    float p0 = h0 * w0.x + h1 * w0.z + h2 * w1.x + h3 * w1.z
             + h4 * w2.x + h5 * w2.z + h6 * w3.x + h7 * w3.z;
    float p1 = h0 * w0.y + h1 * w0.w + h2 * w1.y + h3 * w1.w
             + h4 * w2.y + h5 * w2.w + h6 * w3.y + h7 * w3.w;
    #pragma unroll
    for (int off = 8; off > 0; off >>= 1) {
        p0 += __shfl_xor_sync(0xffffffffu, p0, off);
        p1 += __shfl_xor_sync(0xffffffffu, p1, off);
    }
    if (l16 == 0) {
        g_small[w * 2 + 0] = p0 * d;
        g_small[w * 2 + 1] = p1 * d;
    }
}

__global__ void k_agg_out(const float* __restrict__ b3, float* __restrict__ O) {
    int n = blockIdx.x * blockDim.x + threadIdx.x;
    if (n >= NN) return;
    float ax = g_small[n * 2 + 0];
    float ay = g_small[n * 2 + 1];
    int beg = g_rowstart[n], end = g_rowstart[n + 1];
    for (int e = beg; e < end; e++) {
        int s = g_csr[e];
        float2 v = *(const float2*)&g_small[s * 2];
        ax += v.x;
        ay += v.y;
    }
    float d = g_dinv[n];
    O[n * 2 + 0] = ax * d + b3[0];
    O[n * 2 + 1] = ay * d + b3[1];
}

// ---- static init: materialize globals, smem attrs, side stream + events --------
namespace {
cudaStream_t s_side = nullptr;
cudaEvent_t  s_ev_fork = nullptr, s_ev_det = nullptr, s_ev_fork2 = nullptr,
             s_ev_join = nullptr;
struct ModulePreload {
    ModulePreload() {
        void* p = nullptr;
        cudaGetSymbolAddress(&p, g_bufH);
        cudaFuncSetAttribute((const void*)k_gemm_tc<0>,
                             cudaFuncAttributeMaxDynamicSharedMemorySize, GEMM_SMEM);
        cudaFuncSetAttribute((const void*)k_gemm_tc<1>,
                             cudaFuncAttributeMaxDynamicSharedMemorySize, GEMM_SMEM);
        cudaStreamCreateWithFlags(&s_side, cudaStreamNonBlocking);
        cudaEventCreateWithFlags(&s_ev_fork, cudaEventDisableTiming);
        cudaEventCreateWithFlags(&s_ev_det, cudaEventDisableTiming);
        cudaEventCreateWithFlags(&s_ev_fork2, cudaEventDisableTiming);
        cudaEventCreateWithFlags(&s_ev_join, cudaEventDisableTiming);
    }
};
static ModulePreload s_module_preload;
}

// ---------------- launch ----------------
extern "C" void kernel_launch(void* const* d_in, const int* in_sizes, int n_in,
                              void* d_out, int out_size) {
    const float* x   = (const float*)d_in[0];
    const void*  ei  = d_in[1];
    const float* W1  = (const float*)d_in[2];
    const float* b1  = (const float*)d_in[3];
    const float* ga1 = (const float*)d_in[4];
    const float* be1 = (const float*)d_in[5];
    const float* rm1 = (const float*)d_in[6];
    const float* rv1 = (const float*)d_in[7];
    const float* W2  = (const float*)d_in[8];
    const float* b2  = (const float*)d_in[9];
    const float* ga2 = (const float*)d_in[10];
    const float* be2 = (const float*)d_in[11];
    const float* rm2 = (const float*)d_in[12];
    const float* rv2 = (const float*)d_in[13];
    const float* W3  = (const float*)d_in[14];
    const float* b3  = (const float*)d_in[15];
    float* out = (float*)d_out;

    const int TPB = 256;
    int gridN    = (NN + TPB - 1) / TPB;
    int gridE    = (EE + TPB - 1) / TPB;
    int gridTC   = NN_PAD / 128;                          // 782
    int gridAgg1 = NN_PAD / (TPB / 16);                   // 6256 (half-warp/node)
    int gridAgg2 = (NN + (TPB / 16) - 1) / (TPB / 16);    // 6250

    // fork detect onto side stream; main does weights prep + zero
    cudaEventRecord(s_ev_fork, 0);
    cudaStreamWaitEvent(s_side, s_ev_fork, 0);
    k_detect<<<1, 32, 0, s_side>>>(ei);
    cudaEventRecord(s_ev_det, s_side);

    k_bnparams<<<1, 128>>>(b1, ga1, be1, rm1, rv1, b2, ga2, be2, rm2, rv2);
    k_cvt_w<<<(2 * HID * HID + TPB - 1) / TPB, TPB>>>(W1, W2);
    k_zero<<<gridN, TPB>>>();
    cudaStreamWaitEvent(0, s_ev_det, 0);
    k_count<<<gridE, TPB>>>(ei);
    k_scan1<<<SCAN_NB, SCAN_B>>>();          // produces g_dinv + block sums

    // fork CSR tail (scan2/scan3/fill) to side; main runs GEMM1
    cudaEventRecord(s_ev_fork2, 0);
    cudaStreamWaitEvent(s_side, s_ev_fork2, 0);
    k_scan2<<<1, 128, 0, s_side>>>();
    k_scan3<<<SCAN_NB, SCAN_B, 0, s_side>>>();
    k_fill<<<gridE, TPB, 0, s_side>>>(ei);
    cudaEventRecord(s_ev_join, s_side);

    // main: GEMM1 needs only g_dinv + g_w1h
    k_gemm_tc<0><<<gridTC, TPB, GEMM_SMEM>>>(x);

    // join before aggregation (needs CSR)
    cudaStreamWaitEvent(0, s_ev_join, 0);

    k_agg1<<<gridAgg1, TPB>>>();
    k_gemm_tc<1><<<gridTC, TPB, GEMM_SMEM>>>(nullptr);
    k_agg2<<<gridAgg2, TPB>>>(W3);
    k_agg_out<<<gridN, TPB>>>(b3, out);
}

// round 16
// speedup vs baseline: 1.0504x; 1.0023x over previous
#include <cuda_runtime.h>
#include <cuda_fp16.h>
#include <mma.h>

using namespace nvcuda;

#define NN 100000
#define NN_PAD 100096                     // 782 * 128
#define EE 1600000
#define HID 128
#define NC 2
#define BN_EPS 1e-5f
#define SCAN_B 1024
#define SCAN_NB ((NN + SCAN_B - 1) / SCAN_B)   // 98
#define LDS 136                                 // smem leading dim (half)
#define GEMM_SMEM (2 * 128 * LDS * (int)sizeof(__half))   // 69632 B

// ---------------- scratch (device globals; no allocation allowed) ----------------
__device__ __half g_bufH[(size_t)NN * HID];     // GEMM output = agg input, fp16
__device__ __half g_abuf[(size_t)NN_PAD * HID]; // agg1 output (h * dinv) = GEMM2 A
__device__ __half g_w1h[HID * HID];
__device__ __half g_w2h[HID * HID];
__device__ float  g_small[NN * NC];             // fused layer-3 row results
__device__ int    g_deg[NN];
__device__ float  g_dinv[NN];
__device__ int    g_rowstart[NN + 1];
__device__ int    g_blocksum[SCAN_NB];
__device__ int    g_blockoff[SCAN_NB];
__device__ int    g_fill[NN];
__device__ int    g_csr[EE];
__device__ float  g_sc1[HID], g_sh1[HID], g_sc2[HID], g_sh2[HID];
__device__ int    g_is64;

// ---------------- edge dtype detection (parallel) ----------------
__global__ void k_detect(const void* __restrict__ ei) {
    int tid = threadIdx.x;   // 32 threads
    const long long* p = (const long long*)ei;
    int bad = 0;
    #pragma unroll
    for (int k = 0; k < 2; k++) {
        long long v = p[(tid * 2 + k) * 997];
        bad |= (v < 0 || v >= NN) ? 1 : 0;
    }
    unsigned m = __ballot_sync(0xffffffffu, bad);
    if (tid == 0) g_is64 = (m == 0) ? 1 : 0;
}

__device__ __forceinline__ int edge_at(const void* ei, size_t idx) {
    if (g_is64) return (int)((const long long*)ei)[idx];
    return ((const int*)ei)[idx];
}

// ---------------- CSR build ----------------
__global__ void k_zero() {
    int i = blockIdx.x * blockDim.x + threadIdx.x;
    if (i < NN) { g_deg[i] = 0; g_fill[i] = 0; }
}

// vectorized count: 4 edges per thread (EE divisible by 4)
__global__ void k_count4(const void* __restrict__ ei) {
    int t = blockIdx.x * blockDim.x + threadIdx.x;
    int e = t * 4;
    if (e >= EE) return;
    if (g_is64) {
        const longlong2* p = (const longlong2*)((const long long*)ei + EE + e);
        longlong2 a = p[0];
        longlong2 b = p[1];
        atomicAdd(&g_deg[(int)a.x], 1);
        atomicAdd(&g_deg[(int)a.y], 1);
        atomicAdd(&g_deg[(int)b.x], 1);
        atomicAdd(&g_deg[(int)b.y], 1);
    } else {
        int4 v = *(const int4*)((const int*)ei + EE + e);
        atomicAdd(&g_deg[v.x], 1);
        atomicAdd(&g_deg[v.y], 1);
        atomicAdd(&g_deg[v.z], 1);
        atomicAdd(&g_deg[v.w], 1);
    }
}

__global__ void k_scan1() {
    __shared__ int warpsum[32];
    int tid = threadIdx.x;
    int i = blockIdx.x * SCAN_B + tid;
    int v = (i < NN) ? g_deg[i] : 0;
    if (i < NN) g_dinv[i] = rsqrtf((float)(v + 1));   // +1 self-loop
    int lane = tid & 31, warp = tid >> 5;
    int s = v;
    #pragma unroll
    for (int off = 1; off < 32; off <<= 1) {
        int t = __shfl_up_sync(0xffffffffu, s, off);
        if (lane >= off) s += t;
    }
    if (lane == 31) warpsum[warp] = s;
    __syncthreads();
    if (warp == 0) {
        int ws = (lane < SCAN_B / 32) ? warpsum[lane] : 0;
        #pragma unroll
        for (int off = 1; off < 32; off <<= 1) {
            int t = __shfl_up_sync(0xffffffffu, ws, off);
            if (lane >= off) ws += t;
        }
        warpsum[lane] = ws;
    }
    __syncthreads();
    int base = (warp > 0) ? warpsum[warp - 1] : 0;
    if (i < NN) g_rowstart[i] = base + s - v;
    if (tid == SCAN_B - 1) g_blocksum[blockIdx.x] = base + s;
}

__global__ void k_scan2() {
    __shared__ int sh[128];
    int tid = threadIdx.x;
    int v = (tid < SCAN_NB) ? g_blocksum[tid] : 0;
    int lane = tid & 31, warp = tid >> 5;
    int s = v;
    #pragma unroll
    for (int off = 1; off < 32; off <<= 1) {
        int t = __shfl_up_sync(0xffffffffu, s, off);
        if (lane >= off) s += t;
    }
    if (lane == 31) sh[warp] = s;
    __syncthreads();
    if (warp == 0 && lane < 4) {
        int ws = sh[lane];
        #pragma unroll
        for (int off = 1; off < 4; off <<= 1) {
            int t = __shfl_up_sync(0x0000000fu, ws, off);
            if (lane >= off) ws += t;
        }
        sh[lane] = ws;
    }
    __syncthreads();
    int base = (warp > 0) ? sh[warp - 1] : 0;
    if (tid < SCAN_NB) g_blockoff[tid] = base + s - v;
    if (tid == 127) g_rowstart[NN] = base + s;
}

__global__ void k_scan3() {
    int i = blockIdx.x * SCAN_B + threadIdx.x;
    if (i < NN) g_rowstart[i] += g_blockoff[blockIdx.x];
}

__global__ void k_fill(const void* __restrict__ ei) {
    int e = blockIdx.x * blockDim.x + threadIdx.x;
    if (e < EE) {
        int d = edge_at(ei, (size_t)EE + e);
        int s = edge_at(ei, e);
        int p = atomicAdd(&g_fill[d], 1);
        g_csr[g_rowstart[d] + p] = s;
    }
}

// ---------------- prep: BN folding + weight fp16 conversion (one kernel) --------
__global__ void k_prep(const float* __restrict__ b1, const float* __restrict__ ga1,
                       const float* __restrict__ be1, const float* __restrict__ rm1,
                       const float* __restrict__ rv1,
                       const float* __restrict__ b2, const float* __restrict__ ga2,
                       const float* __restrict__ be2, const float* __restrict__ rm2,
                       const float* __restrict__ rv2,
                       const float* __restrict__ W1, const float* __restrict__ W2) {
    if (blockIdx.x == 128) {
        int c = threadIdx.x;
        if (c < HID) {
            float s1 = ga1[c] * rsqrtf(rv1[c] + BN_EPS);
            g_sc1[c] = s1;
            g_sh1[c] = (b1[c] - rm1[c]) * s1 + be1[c];
            float s2 = ga2[c] * rsqrtf(rv2[c] + BN_EPS);
            g_sc2[c] = s2;
            g_sh2[c] = (b2[c] - rm2[c]) * s2 + be2[c];
        }
        return;
    }
    int i = blockIdx.x * 256 + threadIdx.x;   // 128 blocks * 256 = 32768 = 2*HID*HID
    if (i < HID * HID) g_w1h[i] = __float2half(W1[i]);
    else g_w2h[i - HID * HID] = __float2half(W2[i - HID * HID]);
}

// ---------------- tensor-core GEMM, smem-staged 128x128 tile --------------------
// SRC=0: A = x (fp32, scaled by dinv during staging), W = g_w1h
// SRC=1: A = g_abuf (fp16, already scaled),           W = g_w2h
template <int SRC>
__global__ void k_gemm_tc(const float* __restrict__ X) {
    extern __shared__ __half smem[];
    __half* sA = smem;                 // [128][LDS]
    __half* sW = smem + 128 * LDS;     // [128][LDS]
    __shared__ __align__(16) float scratch[8][16][20];

    int tid = threadIdx.x;
    int row0 = blockIdx.x * 128;

    {
        const __half* __restrict__ Wh = (SRC == 0) ? g_w1h : g_w2h;
        for (int i = tid; i < 128 * 16; i += 256) {
            int r = i >> 4, q = i & 15;
            uint4 v = *(const uint4*)&Wh[r * HID + q * 8];
            *(uint4*)&sW[r * LDS + q * 8] = v;
        }
    }
    if (SRC == 0) {
        for (int i = tid; i < 128 * 32; i += 256) {
            int r = i >> 5, q = i & 31;
            int gr = row0 + r;
            __half2 h01, h23;
            if (gr < NN) {
                float4 v = *(const float4*)&X[(size_t)gr * HID + q * 4];
                float d = g_dinv[gr];
                h01 = __floats2half2_rn(v.x * d, v.y * d);
                h23 = __floats2half2_rn(v.z * d, v.w * d);
            } else {
                h01 = __floats2half2_rn(0.f, 0.f);
                h23 = h01;
            }
            uint2 p;
            p.x = *(unsigned int*)&h01;
            p.y = *(unsigned int*)&h23;
            *(uint2*)&sA[r * LDS + q * 4] = p;
        }
    } else {
        for (int i = tid; i < 128 * 16; i += 256) {
            int r = i >> 4, q = i & 15;
            int gr = row0 + r;     // g_abuf padded to NN_PAD with zeros
            uint4 v = *(const uint4*)&g_abuf[(size_t)gr * HID + q * 8];
            *(uint4*)&sA[r * LDS + q * 8] = v;
        }
    }
    __syncthreads();

    int warp = tid >> 5, lane = tid & 31;
    int rg = warp >> 1, cg = warp & 1;
    int wr0 = rg * 32, col0 = cg * 64;

    wmma::fragment<wmma::accumulator, 16, 16, 16, float> c[2][4];
    #pragma unroll
    for (int i = 0; i < 2; i++)
        #pragma unroll
        for (int j = 0; j < 4; j++) wmma::fill_fragment(c[i][j], 0.f);

    #pragma unroll
    for (int k = 0; k < HID; k += 16) {
        wmma::fragment<wmma::matrix_a, 16, 16, 16, __half, wmma::row_major> a[2];
        wmma::fragment<wmma::matrix_b, 16, 16, 16, __half, wmma::row_major> b[4];
        wmma::load_matrix_sync(a[0], sA + (wr0 + 0) * LDS + k, LDS);
        wmma::load_matrix_sync(a[1], sA + (wr0 + 16) * LDS + k, LDS);
        #pragma unroll
        for (int j = 0; j < 4; j++)
            wmma::load_matrix_sync(b[j], sW + k * LDS + col0 + j * 16, LDS);
        #pragma unroll
        for (int i = 0; i < 2; i++)
            #pragma unroll
            for (int j = 0; j < 4; j++)
                wmma::mma_sync(c[i][j], a[i], b[j], c[i][j]);
    }

    #pragma unroll
    for (int i = 0; i < 2; i++) {
        #pragma unroll
        for (int j = 0; j < 4; j++) {
            wmma::store_matrix_sync(&scratch[warp][0][0], c[i][j], 20, wmma::mem_row_major);
            __syncwarp();
            int r = lane >> 1, ch = lane & 1;
            int gr = row0 + wr0 + i * 16 + r;
            if (gr < NN) {
                int gc = col0 + j * 16 + ch * 8;
                const float* s = &scratch[warp][r][ch * 8];
                __half2 h0 = __floats2half2_rn(s[0], s[1]);
                __half2 h1 = __floats2half2_rn(s[2], s[3]);
                __half2 h2 = __floats2half2_rn(s[4], s[5]);
                __half2 h3 = __floats2half2_rn(s[6], s[7]);
                uint4 p;
                p.x = *(unsigned int*)&h0;
                p.y = *(unsigned int*)&h1;
                p.z = *(unsigned int*)&h2;
                p.w = *(unsigned int*)&h3;
                *(uint4*)&g_bufH[(size_t)gr * HID + gc] = p;
            }
            __syncwarp();
        }
    }
}

// ---- gather body: HALF-WARP per node, uint4 (LDG.128) lanes, 2-wide unroll -----
__device__ __forceinline__ void agg_gather8(int w, int c0, float a[8]) {
    int beg = g_rowstart[w], end = g_rowstart[w + 1];
    {
        uint4 p = *(const uint4*)&g_bufH[(size_t)w * HID + c0];
        float2 f0 = __half22float2(*(__half2*)&p.x);
        float2 f1 = __half22float2(*(__half2*)&p.y);
        float2 f2 = __half22float2(*(__half2*)&p.z);
        float2 f3 = __half22float2(*(__half2*)&p.w);
        a[0] = f0.x; a[1] = f0.y; a[2] = f1.x; a[3] = f1.y;
        a[4] = f2.x; a[5] = f2.y; a[6] = f3.x; a[7] = f3.y;
    }
    int e = beg;
    for (; e + 2 <= end; e += 2) {
        int s0 = g_csr[e];
        int s1 = g_csr[e + 1];
        uint4 p0 = *(const uint4*)&g_bufH[(size_t)s0 * HID + c0];
        uint4 p1 = *(const uint4*)&g_bufH[(size_t)s1 * HID + c0];
        float2 f0 = __half22float2(*(__half2*)&p0.x);
        float2 f1 = __half22float2(*(__half2*)&p0.y);
        float2 f2 = __half22float2(*(__half2*)&p0.z);
        float2 f3 = __half22float2(*(__half2*)&p0.w);
        float2 g0 = __half22float2(*(__half2*)&p1.x);
        float2 g1 = __half22float2(*(__half2*)&p1.y);
        float2 g2 = __half22float2(*(__half2*)&p1.z);
        float2 g3 = __half22float2(*(__half2*)&p1.w);
        a[0] += f0.x + g0.x; a[1] += f0.y + g0.y;
        a[2] += f1.x + g1.x; a[3] += f1.y + g1.y;
        a[4] += f2.x + g2.x; a[5] += f2.y + g2.y;
        a[6] += f3.x + g3.x; a[7] += f3.y + g3.y;
    }
    if (e < end) {
        int s0 = g_csr[e];
        uint4 p0 = *(const uint4*)&g_bufH[(size_t)s0 * HID + c0];
        float2 f0 = __half22float2(*(__half2*)&p0.x);
        float2 f1 = __half22float2(*(__half2*)&p0.y);
        float2 f2 = __half22float2(*(__half2*)&p0.z);
        float2 f3 = __half22float2(*(__half2*)&p0.w);
        a[0] += f0.x; a[1] += f0.y; a[2] += f1.x; a[3] += f1.y;
        a[4] += f2.x; a[5] += f2.y; a[6] += f3.x; a[7] += f3.y;
    }
}

// ---------------- agg layer 1: gather -> BN/ReLU -> *dinv -> g_abuf -------------
__global__ void k_agg1() {
    int w = (blockIdx.x * blockDim.x + threadIdx.x) >> 4;    // half-warp per node
    int l16 = threadIdx.x & 15;
    int c0 = l16 * 8;
    if (w >= NN) {
        if (w < NN_PAD) {
            uint4 p;
            p.x = p.y = p.z = p.w = 0u;
            *(uint4*)&g_abuf[(size_t)w * HID + c0] = p;
        }
        return;
    }
    float a[8];
    agg_gather8(w, c0, a);
    float d = g_dinv[w];
    float4 s4a = *(const float4*)&g_sc1[c0];
    float4 s4b = *(const float4*)&g_sc1[c0 + 4];
    float4 h4a = *(const float4*)&g_sh1[c0];
    float4 h4b = *(const float4*)&g_sh1[c0 + 4];
    float o0 = fmaxf(a[0] * d * s4a.x + h4a.x, 0.f) * d;
    float o1 = fmaxf(a[1] * d * s4a.y + h4a.y, 0.f) * d;
    float o2 = fmaxf(a[2] * d * s4a.z + h4a.z, 0.f) * d;
    float o3 = fmaxf(a[3] * d * s4a.w + h4a.w, 0.f) * d;
    float o4 = fmaxf(a[4] * d * s4b.x + h4b.x, 0.f) * d;
    float o5 = fmaxf(a[5] * d * s4b.y + h4b.y, 0.f) * d;
    float o6 = fmaxf(a[6] * d * s4b.z + h4b.z, 0.f) * d;
    float o7 = fmaxf(a[7] * d * s4b.w + h4b.w, 0.f) * d;
    __half2 q0 = __floats2half2_rn(o0, o1);
    __half2 q1 = __floats2half2_rn(o2, o3);
    __half2 q2 = __floats2half2_rn(o4, o5);
    __half2 q3 = __floats2half2_rn(o6, o7);
    uint4 p;
    p.x = *(unsigned int*)&q0;
    p.y = *(unsigned int*)&q1;
    p.z = *(unsigned int*)&q2;
    p.w = *(unsigned int*)&q3;
    *(uint4*)&g_abuf[(size_t)w * HID + c0] = p;
}

// ---- agg layer 2: gather -> BN/ReLU -> fused 128->2 dot with W3 -> g_small -----
__global__ void k_agg2(const float* __restrict__ W3) {
    int w = (blockIdx.x * blockDim.x + threadIdx.x) >> 4;    // half-warp per node
    int l16 = threadIdx.x & 15;
    int c0 = l16 * 8;
    if (w >= NN) return;
    float a[8];
    agg_gather8(w, c0, a);
    float d = g_dinv[w];
    float4 s4a = *(const float4*)&g_sc2[c0];
    float4 s4b = *(const float4*)&g_sc2[c0 + 4];
    float4 h4a = *(const float4*)&g_sh2[c0];
    float4 h4b = *(const float4*)&g_sh2[c0 + 4];
    float h0 = fmaxf(a[0] * d * s4a.x + h4a.x, 0.f);
    float h1 = fmaxf(a[1] * d * s4a.y + h4a.y, 0.f);
    float h2 = fmaxf(a[2] * d * s4a.z + h4a.z, 0.f);
    float h3 = fmaxf(a[3] * d * s4a.w + h4a.w, 0.f);
    float h4 = fmaxf(a[4] * d * s4b.x + h4b.x, 0.f);
    float h5 = fmaxf(a[5] * d * s4b.y + h4b.y, 0.f);
    float h6 = fmaxf(a[6] * d * s4b.z + h4b.z, 0.f);
    float h7 = fmaxf(a[7] * d * s4b.w + h4b.w, 0.f);
    // W3 rows c0..c0+7, 2 cols each: 16 consecutive floats
    float4 w0 = *(const float4*)&W3[c0 * 2];
    float4 w1 = *(const float4*)&W3[c0 * 2 + 4];
    float4 w2 = *(const float4*)&W3[c0 * 2 + 8];
    float4 w3 = *(const float4*)&W3[c0 * 2 + 12];
    float p0 = h0 * w0.x + h1 * w0.z + h2 * w1.x + h3 * w1.z
             + h4 * w2.x + h5 * w2.z + h6 * w3.x + h7 * w3.z;
    float p1 = h0 * w0.y + h1 * w0.w + h2 * w1.y + h3 * w1.w
             + h4 * w2.y + h5 * w2.w + h6 * w3.y + h7 * w3.w;
    #pragma unroll
    for (int off = 8; off > 0; off >>= 1) {
        p0 += __shfl_xor_sync(0xffffffffu, p0, off);
        p1 += __shfl_xor_sync(0xffffffffu, p1, off);
    }
    if (l16 == 0) {
        g_small[w * 2 + 0] = p0 * d;
        g_small[w * 2 + 1] = p1 * d;
    }
}

__global__ void k_agg_out(const float* __restrict__ b3, float* __restrict__ O) {
    int n = blockIdx.x * blockDim.x + threadIdx.x;
    if (n >= NN) return;
    float ax = g_small[n * 2 + 0];
    float ay = g_small[n * 2 + 1];
    int beg = g_rowstart[n], end = g_rowstart[n + 1];
    for (int e = beg; e < end; e++) {
        int s = g_csr[e];
        float2 v = *(const float2*)&g_small[s * 2];
        ax += v.x;
        ay += v.y;
    }
    float d = g_dinv[n];
    O[n * 2 + 0] = ax * d + b3[0];
    O[n * 2 + 1] = ay * d + b3[1];
}

// ---- static init: materialize globals, smem attrs, side stream + events --------
namespace {
cudaStream_t s_side = nullptr;
cudaEvent_t  s_ev_fork = nullptr, s_ev_det = nullptr, s_ev_prep = nullptr,
             s_ev_fork2 = nullptr, s_ev_join = nullptr;
struct ModulePreload {
    ModulePreload() {
        void* p = nullptr;
        cudaGetSymbolAddress(&p, g_bufH);
        cudaFuncSetAttribute((const void*)k_gemm_tc<0>,
                             cudaFuncAttributeMaxDynamicSharedMemorySize, GEMM_SMEM);
        cudaFuncSetAttribute((const void*)k_gemm_tc<1>,
                             cudaFuncAttributeMaxDynamicSharedMemorySize, GEMM_SMEM);
        cudaStreamCreateWithFlags(&s_side, cudaStreamNonBlocking);
        cudaEventCreateWithFlags(&s_ev_fork, cudaEventDisableTiming);
        cudaEventCreateWithFlags(&s_ev_det, cudaEventDisableTiming);
        cudaEventCreateWithFlags(&s_ev_prep, cudaEventDisableTiming);
        cudaEventCreateWithFlags(&s_ev_fork2, cudaEventDisableTiming);
        cudaEventCreateWithFlags(&s_ev_join, cudaEventDisableTiming);
    }
};
static ModulePreload s_module_preload;
}

// ---------------- launch ----------------
extern "C" void kernel_launch(void* const* d_in, const int* in_sizes, int n_in,
                              void* d_out, int out_size) {
    const float* x   = (const float*)d_in[0];
    const void*  ei  = d_in[1];
    const float* W1  = (const float*)d_in[2];
    const float* b1  = (const float*)d_in[3];
    const float* ga1 = (const float*)d_in[4];
    const float* be1 = (const float*)d_in[5];
    const float* rm1 = (const float*)d_in[6];
    const float* rv1 = (const float*)d_in[7];
    const float* W2  = (const float*)d_in[8];
    const float* b2  = (const float*)d_in[9];
    const float* ga2 = (const float*)d_in[10];
    const float* be2 = (const float*)d_in[11];
    const float* rm2 = (const float*)d_in[12];
    const float* rv2 = (const float*)d_in[13];
    const float* W3  = (const float*)d_in[14];
    const float* b3  = (const float*)d_in[15];
    float* out = (float*)d_out;

    const int TPB = 256;
    int gridN    = (NN + TPB - 1) / TPB;
    int gridE    = (EE + TPB - 1) / TPB;
    int gridE4   = (EE / 4 + TPB - 1) / TPB;              // 1563
    int gridTC   = NN_PAD / 128;                          // 782
    int gridAgg1 = NN_PAD / (TPB / 16);                   // 6256 (half-warp/node)
    int gridAgg2 = (NN + (TPB / 16) - 1) / (TPB / 16);    // 6250

    // side stream: detect -> prep (weights fp16 + BN folding), off critical path
    cudaEventRecord(s_ev_fork, 0);
    cudaStreamWaitEvent(s_side, s_ev_fork, 0);
    k_detect<<<1, 32, 0, s_side>>>(ei);
    cudaEventRecord(s_ev_det, s_side);
    k_prep<<<129, 256, 0, s_side>>>(b1, ga1, be1, rm1, rv1,
                                    b2, ga2, be2, rm2, rv2, W1, W2);
    cudaEventRecord(s_ev_prep, s_side);

    // main: zero -> (wait detect) -> count -> scan1
    k_zero<<<gridN, TPB>>>();
    cudaStreamWaitEvent(0, s_ev_det, 0);
    k_count4<<<gridE4, TPB>>>(ei);
    k_scan1<<<SCAN_NB, SCAN_B>>>();          // produces g_dinv + block sums

    // fork CSR tail (scan2/scan3/fill) to side; main runs GEMM1
    cudaEventRecord(s_ev_fork2, 0);
    cudaStreamWaitEvent(s_side, s_ev_fork2, 0);
    k_scan2<<<1, 128, 0, s_side>>>();
    k_scan3<<<SCAN_NB, SCAN_B, 0, s_side>>>();
    k_fill<<<gridE, TPB, 0, s_side>>>(ei);
    cudaEventRecord(s_ev_join, s_side);

    // main: GEMM1 needs g_dinv + g_w1h (prep)
    cudaStreamWaitEvent(0, s_ev_prep, 0);
    k_gemm_tc<0><<<gridTC, TPB, GEMM_SMEM>>>(x);

    // join before aggregation (needs CSR)
    cudaStreamWaitEvent(0, s_ev_join, 0);

    k_agg1<<<gridAgg1, TPB>>>();
    k_gemm_tc<1><<<gridTC, TPB, GEMM_SMEM>>>(nullptr);
    k_agg2<<<gridAgg2, TPB>>>(W3);
    k_agg_out<<<gridN, TPB>>>(b3, out);
}

// round 17
// speedup vs baseline: 1.0567x; 1.0060x over previous
#include <cuda_runtime.h>
#include <cuda_fp16.h>
#include <mma.h>

using namespace nvcuda;

#define NN 100000
#define NN_PAD 100096                     // 782 * 128
#define EE 1600000
#define HID 128
#define NC 2
#define BN_EPS 1e-5f
#define SCAN_B 1024
#define SCAN_NB ((NN + SCAN_B - 1) / SCAN_B)   // 98
#define LDS 136                                 // smem leading dim (half)
#define GEMM_SMEM (2 * 128 * LDS * (int)sizeof(__half))   // 69632 B

// ---------------- scratch (device globals; no allocation allowed) ----------------
__device__ __half g_bufH[(size_t)NN * HID];     // GEMM output = agg input, fp16
__device__ __half g_abuf[(size_t)NN_PAD * HID]; // agg1 output (h * dinv) = GEMM2 A
__device__ __half g_w1h[HID * HID];
__device__ __half g_w2h[HID * HID];
__device__ float  g_small[NN * NC];             // fused layer-3 row results
__device__ int    g_deg[NN];
__device__ float  g_dinv[NN];
__device__ int    g_rowstart[NN + 1];
__device__ int    g_blocksum[SCAN_NB];
__device__ int    g_blockoff[SCAN_NB];
__device__ int    g_fill[NN];
__device__ int    g_csr[EE];
__device__ float  g_sc1[HID], g_sh1[HID], g_sc2[HID], g_sh2[HID];
__device__ int    g_is64;

// ---------------- edge dtype detection (parallel) ----------------
__global__ void k_detect(const void* __restrict__ ei) {
    int tid = threadIdx.x;   // 32 threads
    const long long* p = (const long long*)ei;
    int bad = 0;
    #pragma unroll
    for (int k = 0; k < 2; k++) {
        long long v = p[(tid * 2 + k) * 997];
        bad |= (v < 0 || v >= NN) ? 1 : 0;
    }
    unsigned m = __ballot_sync(0xffffffffu, bad);
    if (tid == 0) g_is64 = (m == 0) ? 1 : 0;
}

__device__ __forceinline__ int edge_at(const void* ei, size_t idx) {
    if (g_is64) return (int)((const long long*)ei)[idx];
    return ((const int*)ei)[idx];
}

// ---------------- CSR build ----------------
__global__ void k_zero() {
    int i = blockIdx.x * blockDim.x + threadIdx.x;
    if (i < NN) { g_deg[i] = 0; g_fill[i] = 0; }
}

// scalar count (measured faster than 4-wide: atomic-throughput bound, wants
// maximal warp-level parallelism feeding the LTS atomic units)
__global__ void k_count(const void* __restrict__ ei) {
    int e = blockIdx.x * blockDim.x + threadIdx.x;
    if (e < EE) atomicAdd(&g_deg[edge_at(ei, (size_t)EE + e)], 1);
}

__global__ void k_scan1() {
    __shared__ int warpsum[32];
    int tid = threadIdx.x;
    int i = blockIdx.x * SCAN_B + tid;
    int v = (i < NN) ? g_deg[i] : 0;
    if (i < NN) g_dinv[i] = rsqrtf((float)(v + 1));   // +1 self-loop
    int lane = tid & 31, warp = tid >> 5;
    int s = v;
    #pragma unroll
    for (int off = 1; off < 32; off <<= 1) {
        int t = __shfl_up_sync(0xffffffffu, s, off);
        if (lane >= off) s += t;
    }
    if (lane == 31) warpsum[warp] = s;
    __syncthreads();
    if (warp == 0) {
        int ws = (lane < SCAN_B / 32) ? warpsum[lane] : 0;
        #pragma unroll
        for (int off = 1; off < 32; off <<= 1) {
            int t = __shfl_up_sync(0xffffffffu, ws, off);
            if (lane >= off) ws += t;
        }
        warpsum[lane] = ws;
    }
    __syncthreads();
    int base = (warp > 0) ? warpsum[warp - 1] : 0;
    if (i < NN) g_rowstart[i] = base + s - v;
    if (tid == SCAN_B - 1) g_blocksum[blockIdx.x] = base + s;
}

__global__ void k_scan2() {
    __shared__ int sh[128];
    int tid = threadIdx.x;
    int v = (tid < SCAN_NB) ? g_blocksum[tid] : 0;
    int lane = tid & 31, warp = tid >> 5;
    int s = v;
    #pragma unroll
    for (int off = 1; off < 32; off <<= 1) {
        int t = __shfl_up_sync(0xffffffffu, s, off);
        if (lane >= off) s += t;
    }
    if (lane == 31) sh[warp] = s;
    __syncthreads();
    if (warp == 0 && lane < 4) {
        int ws = sh[lane];
        #pragma unroll
        for (int off = 1; off < 4; off <<= 1) {
            int t = __shfl_up_sync(0x0000000fu, ws, off);
            if (lane >= off) ws += t;
        }
        sh[lane] = ws;
    }
    __syncthreads();
    int base = (warp > 0) ? sh[warp - 1] : 0;
    if (tid < SCAN_NB) g_blockoff[tid] = base + s - v;
    if (tid == 127) g_rowstart[NN] = base + s;
}

__global__ void k_scan3() {
    int i = blockIdx.x * SCAN_B + threadIdx.x;
    if (i < NN) g_rowstart[i] += g_blockoff[blockIdx.x];
}

__global__ void k_fill(const void* __restrict__ ei) {
    int e = blockIdx.x * blockDim.x + threadIdx.x;
    if (e < EE) {
        int d = edge_at(ei, (size_t)EE + e);
        int s = edge_at(ei, e);
        int p = atomicAdd(&g_fill[d], 1);
        g_csr[g_rowstart[d] + p] = s;
    }
}

// ---------------- prep: BN folding + weight fp16 conversion (one kernel) --------
__global__ void k_prep(const float* __restrict__ b1, const float* __restrict__ ga1,
                       const float* __restrict__ be1, const float* __restrict__ rm1,
                       const float* __restrict__ rv1,
                       const float* __restrict__ b2, const float* __restrict__ ga2,
                       const float* __restrict__ be2, const float* __restrict__ rm2,
                       const float* __restrict__ rv2,
                       const float* __restrict__ W1, const float* __restrict__ W2) {
    if (blockIdx.x == 128) {
        int c = threadIdx.x;
        if (c < HID) {
            float s1 = ga1[c] * rsqrtf(rv1[c] + BN_EPS);
            g_sc1[c] = s1;
            g_sh1[c] = (b1[c] - rm1[c]) * s1 + be1[c];
            float s2 = ga2[c] * rsqrtf(rv2[c] + BN_EPS);
            g_sc2[c] = s2;
            g_sh2[c] = (b2[c] - rm2[c]) * s2 + be2[c];
        }
        return;
    }
    int i = blockIdx.x * 256 + threadIdx.x;   // 128 blocks * 256 = 32768 = 2*HID*HID
    if (i < HID * HID) g_w1h[i] = __float2half(W1[i]);
    else g_w2h[i - HID * HID] = __float2half(W2[i - HID * HID]);
}

// ---------------- tensor-core GEMM, smem-staged 128x128 tile --------------------
// SRC=0: A = x (fp32, scaled by dinv during staging), W = g_w1h
// SRC=1: A = g_abuf (fp16, already scaled),           W = g_w2h
template <int SRC>
__global__ void k_gemm_tc(const float* __restrict__ X) {
    extern __shared__ __half smem[];
    __half* sA = smem;                 // [128][LDS]
    __half* sW = smem + 128 * LDS;     // [128][LDS]
    __shared__ __align__(16) float scratch[8][16][20];

    int tid = threadIdx.x;
    int row0 = blockIdx.x * 128;

    {
        const __half* __restrict__ Wh = (SRC == 0) ? g_w1h : g_w2h;
        for (int i = tid; i < 128 * 16; i += 256) {
            int r = i >> 4, q = i & 15;
            uint4 v = *(const uint4*)&Wh[r * HID + q * 8];
            *(uint4*)&sW[r * LDS + q * 8] = v;
        }
    }
    if (SRC == 0) {
        for (int i = tid; i < 128 * 32; i += 256) {
            int r = i >> 5, q = i & 31;
            int gr = row0 + r;
            __half2 h01, h23;
            if (gr < NN) {
                float4 v = *(const float4*)&X[(size_t)gr * HID + q * 4];
                float d = g_dinv[gr];
                h01 = __floats2half2_rn(v.x * d, v.y * d);
                h23 = __floats2half2_rn(v.z * d, v.w * d);
            } else {
                h01 = __floats2half2_rn(0.f, 0.f);
                h23 = h01;
            }
            uint2 p;
            p.x = *(unsigned int*)&h01;
            p.y = *(unsigned int*)&h23;
            *(uint2*)&sA[r * LDS + q * 4] = p;
        }
    } else {
        for (int i = tid; i < 128 * 16; i += 256) {
            int r = i >> 4, q = i & 15;
            int gr = row0 + r;     // g_abuf padded to NN_PAD with zeros
            uint4 v = *(const uint4*)&g_abuf[(size_t)gr * HID + q * 8];
            *(uint4*)&sA[r * LDS + q * 8] = v;
        }
    }
    __syncthreads();

    int warp = tid >> 5, lane = tid & 31;
    int rg = warp >> 1, cg = warp & 1;
    int wr0 = rg * 32, col0 = cg * 64;

    wmma::fragment<wmma::accumulator, 16, 16, 16, float> c[2][4];
    #pragma unroll
    for (int i = 0; i < 2; i++)
        #pragma unroll
        for (int j = 0; j < 4; j++) wmma::fill_fragment(c[i][j], 0.f);

    #pragma unroll
    for (int k = 0; k < HID; k += 16) {
        wmma::fragment<wmma::matrix_a, 16, 16, 16, __half, wmma::row_major> a[2];
        wmma::fragment<wmma::matrix_b, 16, 16, 16, __half, wmma::row_major> b[4];
        wmma::load_matrix_sync(a[0], sA + (wr0 + 0) * LDS + k, LDS);
        wmma::load_matrix_sync(a[1], sA + (wr0 + 16) * LDS + k, LDS);
        #pragma unroll
        for (int j = 0; j < 4; j++)
            wmma::load_matrix_sync(b[j], sW + k * LDS + col0 + j * 16, LDS);
        #pragma unroll
        for (int i = 0; i < 2; i++)
            #pragma unroll
            for (int j = 0; j < 4; j++)
                wmma::mma_sync(c[i][j], a[i], b[j], c[i][j]);
    }

    #pragma unroll
    for (int i = 0; i < 2; i++) {
        #pragma unroll
        for (int j = 0; j < 4; j++) {
            wmma::store_matrix_sync(&scratch[warp][0][0], c[i][j], 20, wmma::mem_row_major);
            __syncwarp();
            int r = lane >> 1, ch = lane & 1;
            int gr = row0 + wr0 + i * 16 + r;
            if (gr < NN) {
                int gc = col0 + j * 16 + ch * 8;
                const float* s = &scratch[warp][r][ch * 8];
                __half2 h0 = __floats2half2_rn(s[0], s[1]);
                __half2 h1 = __floats2half2_rn(s[2], s[3]);
                __half2 h2 = __floats2half2_rn(s[4], s[5]);
                __half2 h3 = __floats2half2_rn(s[6], s[7]);
                uint4 p;
                p.x = *(unsigned int*)&h0;
                p.y = *(unsigned int*)&h1;
                p.z = *(unsigned int*)&h2;
                p.w = *(unsigned int*)&h3;
                *(uint4*)&g_bufH[(size_t)gr * HID + gc] = p;
            }
            __syncwarp();
        }
    }
}

// ---- gather body: HALF-WARP per node, uint4 (LDG.128) lanes, 2-wide unroll -----
__device__ __forceinline__ void agg_gather8(int w, int c0, float a[8]) {
    int beg = g_rowstart[w], end = g_rowstart[w + 1];
    {
        uint4 p = *(const uint4*)&g_bufH[(size_t)w * HID + c0];
        float2 f0 = __half22float2(*(__half2*)&p.x);
        float2 f1 = __half22float2(*(__half2*)&p.y);
        float2 f2 = __half22float2(*(__half2*)&p.z);
        float2 f3 = __half22float2(*(__half2*)&p.w);
        a[0] = f0.x; a[1] = f0.y; a[2] = f1.x; a[3] = f1.y;
        a[4] = f2.x; a[5] = f2.y; a[6] = f3.x; a[7] = f3.y;
    }
    int e = beg;
    for (; e + 2 <= end; e += 2) {
        int s0 = g_csr[e];
        int s1 = g_csr[e + 1];
        uint4 p0 = *(const uint4*)&g_bufH[(size_t)s0 * HID + c0];
        uint4 p1 = *(const uint4*)&g_bufH[(size_t)s1 * HID + c0];
        float2 f0 = __half22float2(*(__half2*)&p0.x);
        float2 f1 = __half22float2(*(__half2*)&p0.y);
        float2 f2 = __half22float2(*(__half2*)&p0.z);
        float2 f3 = __half22float2(*(__half2*)&p0.w);
        float2 g0 = __half22float2(*(__half2*)&p1.x);
        float2 g1 = __half22float2(*(__half2*)&p1.y);
        float2 g2 = __half22float2(*(__half2*)&p1.z);
        float2 g3 = __half22float2(*(__half2*)&p1.w);
        a[0] += f0.x + g0.x; a[1] += f0.y + g0.y;
        a[2] += f1.x + g1.x; a[3] += f1.y + g1.y;
        a[4] += f2.x + g2.x; a[5] += f2.y + g2.y;
        a[6] += f3.x + g3.x; a[7] += f3.y + g3.y;
    }
    if (e < end) {
        int s0 = g_csr[e];
        uint4 p0 = *(const uint4*)&g_bufH[(size_t)s0 * HID + c0];
        float2 f0 = __half22float2(*(__half2*)&p0.x);
        float2 f1 = __half22float2(*(__half2*)&p0.y);
        float2 f2 = __half22float2(*(__half2*)&p0.z);
        float2 f3 = __half22float2(*(__half2*)&p0.w);
        a[0] += f0.x; a[1] += f0.y; a[2] += f1.x; a[3] += f1.y;
        a[4] += f2.x; a[5] += f2.y; a[6] += f3.x; a[7] += f3.y;
    }
}

// ---------------- agg layer 1: gather -> BN/ReLU -> *dinv -> g_abuf -------------
__global__ void k_agg1() {
    int w = (blockIdx.x * blockDim.x + threadIdx.x) >> 4;    // half-warp per node
    int l16 = threadIdx.x & 15;
    int c0 = l16 * 8;
    if (w >= NN) {
        if (w < NN_PAD) {
            uint4 p;
            p.x = p.y = p.z = p.w = 0u;
            *(uint4*)&g_abuf[(size_t)w * HID + c0] = p;
        }
        return;
    }
    float a[8];
    agg_gather8(w, c0, a);
    float d = g_dinv[w];
    float4 s4a = *(const float4*)&g_sc1[c0];
    float4 s4b = *(const float4*)&g_sc1[c0 + 4];
    float4 h4a = *(const float4*)&g_sh1[c0];
    float4 h4b = *(const float4*)&g_sh1[c0 + 4];
    float o0 = fmaxf(a[0] * d * s4a.x + h4a.x, 0.f) * d;
    float o1 = fmaxf(a[1] * d * s4a.y + h4a.y, 0.f) * d;
    float o2 = fmaxf(a[2] * d * s4a.z + h4a.z, 0.f) * d;
    float o3 = fmaxf(a[3] * d * s4a.w + h4a.w, 0.f) * d;
    float o4 = fmaxf(a[4] * d * s4b.x + h4b.x, 0.f) * d;
    float o5 = fmaxf(a[5] * d * s4b.y + h4b.y, 0.f) * d;
    float o6 = fmaxf(a[6] * d * s4b.z + h4b.z, 0.f) * d;
    float o7 = fmaxf(a[7] * d * s4b.w + h4b.w, 0.f) * d;
    __half2 q0 = __floats2half2_rn(o0, o1);
    __half2 q1 = __floats2half2_rn(o2, o3);
    __half2 q2 = __floats2half2_rn(o4, o5);
    __half2 q3 = __floats2half2_rn(o6, o7);
    uint4 p;
    p.x = *(unsigned int*)&q0;
    p.y = *(unsigned int*)&q1;
    p.z = *(unsigned int*)&q2;
    p.w = *(unsigned int*)&q3;
    *(uint4*)&g_abuf[(size_t)w * HID + c0] = p;
}

// ---- agg layer 2: gather -> BN/ReLU -> fused 128->2 dot with W3 -> g_small -----
__global__ void k_agg2(const float* __restrict__ W3) {
    int w = (blockIdx.x * blockDim.x + threadIdx.x) >> 4;    // half-warp per node
    int l16 = threadIdx.x & 15;
    int c0 = l16 * 8;
    if (w >= NN) return;
    float a[8];
    agg_gather8(w, c0, a);
    float d = g_dinv[w];
    float4 s4a = *(const float4*)&g_sc2[c0];
    float4 s4b = *(const float4*)&g_sc2[c0 + 4];
    float4 h4a = *(const float4*)&g_sh2[c0];
    float4 h4b = *(const float4*)&g_sh2[c0 + 4];
    float h0 = fmaxf(a[0] * d * s4a.x + h4a.x, 0.f);
    float h1 = fmaxf(a[1] * d * s4a.y + h4a.y, 0.f);
    float h2 = fmaxf(a[2] * d * s4a.z + h4a.z, 0.f);
    float h3 = fmaxf(a[3] * d * s4a.w + h4a.w, 0.f);
    float h4 = fmaxf(a[4] * d * s4b.x + h4b.x, 0.f);
    float h5 = fmaxf(a[5] * d * s4b.y + h4b.y, 0.f);
    float h6 = fmaxf(a[6] * d * s4b.z + h4b.z, 0.f);
    float h7 = fmaxf(a[7] * d * s4b.w + h4b.w, 0.f);
    // W3 rows c0..c0+7, 2 cols each: 16 consecutive floats
    float4 w0 = *(const float4*)&W3[c0 * 2];
    float4 w1 = *(const float4*)&W3[c0 * 2 + 4];
    float4 w2 = *(const float4*)&W3[c0 * 2 + 8];
    float4 w3 = *(const float4*)&W3[c0 * 2 + 12];
    float p0 = h0 * w0.x + h1 * w0.z + h2 * w1.x + h3 * w1.z
             + h4 * w2.x + h5 * w2.z + h6 * w3.x + h7 * w3.z;
    float p1 = h0 * w0.y + h1 * w0.w + h2 * w1.y + h3 * w1.w
             + h4 * w2.y + h5 * w2.w + h6 * w3.y + h7 * w3.w;
    #pragma unroll
    for (int off = 8; off > 0; off >>= 1) {
        p0 += __shfl_xor_sync(0xffffffffu, p0, off);
        p1 += __shfl_xor_sync(0xffffffffu, p1, off);
    }
    if (l16 == 0) {
        g_small[w * 2 + 0] = p0 * d;
        g_small[w * 2 + 1] = p1 * d;
    }
}

// ---- layer-3 aggregation: 4-wide unrolled (MLP) serial loop per node -----------
__global__ void k_agg_out(const float* __restrict__ b3, float* __restrict__ O) {
    int n = blockIdx.x * blockDim.x + threadIdx.x;
    if (n >= NN) return;
    float ax = g_small[n * 2 + 0];
    float ay = g_small[n * 2 + 1];
    int beg = g_rowstart[n], end = g_rowstart[n + 1];
    int e = beg;
    for (; e + 4 <= end; e += 4) {
        int s0 = g_csr[e];
        int s1 = g_csr[e + 1];
        int s2 = g_csr[e + 2];
        int s3 = g_csr[e + 3];
        float2 v0 = *(const float2*)&g_small[s0 * 2];
        float2 v1 = *(const float2*)&g_small[s1 * 2];
        float2 v2 = *(const float2*)&g_small[s2 * 2];
        float2 v3 = *(const float2*)&g_small[s3 * 2];
        ax += (v0.x + v1.x) + (v2.x + v3.x);
        ay += (v0.y + v1.y) + (v2.y + v3.y);
    }
    for (; e < end; e++) {
        int s = g_csr[e];
        float2 v = *(const float2*)&g_small[s * 2];
        ax += v.x;
        ay += v.y;
    }
    float d = g_dinv[n];
    O[n * 2 + 0] = ax * d + b3[0];
    O[n * 2 + 1] = ay * d + b3[1];
}

// ---- static init: materialize globals, smem attrs, side stream + events --------
namespace {
cudaStream_t s_side = nullptr;
cudaEvent_t  s_ev_fork = nullptr, s_ev_det = nullptr, s_ev_prep = nullptr,
             s_ev_fork2 = nullptr, s_ev_join = nullptr;
struct ModulePreload {
    ModulePreload() {
        void* p = nullptr;
        cudaGetSymbolAddress(&p, g_bufH);
        cudaFuncSetAttribute((const void*)k_gemm_tc<0>,
                             cudaFuncAttributeMaxDynamicSharedMemorySize, GEMM_SMEM);
        cudaFuncSetAttribute((const void*)k_gemm_tc<1>,
                             cudaFuncAttributeMaxDynamicSharedMemorySize, GEMM_SMEM);
        cudaStreamCreateWithFlags(&s_side, cudaStreamNonBlocking);
        cudaEventCreateWithFlags(&s_ev_fork, cudaEventDisableTiming);
        cudaEventCreateWithFlags(&s_ev_det, cudaEventDisableTiming);
        cudaEventCreateWithFlags(&s_ev_prep, cudaEventDisableTiming);
        cudaEventCreateWithFlags(&s_ev_fork2, cudaEventDisableTiming);
        cudaEventCreateWithFlags(&s_ev_join, cudaEventDisableTiming);
    }
};
static ModulePreload s_module_preload;
}

// ---------------- launch ----------------
extern "C" void kernel_launch(void* const* d_in, const int* in_sizes, int n_in,
                              void* d_out, int out_size) {
    const float* x   = (const float*)d_in[0];
    const void*  ei  = d_in[1];
    const float* W1  = (const float*)d_in[2];
    const float* b1  = (const float*)d_in[3];
    const float* ga1 = (const float*)d_in[4];
    const float* be1 = (const float*)d_in[5];
    const float* rm1 = (const float*)d_in[6];
    const float* rv1 = (const float*)d_in[7];
    const float* W2  = (const float*)d_in[8];
    const float* b2  = (const float*)d_in[9];
    const float* ga2 = (const float*)d_in[10];
    const float* be2 = (const float*)d_in[11];
    const float* rm2 = (const float*)d_in[12];
    const float* rv2 = (const float*)d_in[13];
    const float* W3  = (const float*)d_in[14];
    const float* b3  = (const float*)d_in[15];
    float* out = (float*)d_out;

    const int TPB = 256;
    int gridN    = (NN + TPB - 1) / TPB;
    int gridE    = (EE + TPB - 1) / TPB;
    int gridTC   = NN_PAD / 128;                          // 782
    int gridAgg1 = NN_PAD / (TPB / 16);                   // 6256 (half-warp/node)
    int gridAgg2 = (NN + (TPB / 16) - 1) / (TPB / 16);    // 6250

    // side stream: detect -> prep (weights fp16 + BN folding), off critical path
    cudaEventRecord(s_ev_fork, 0);
    cudaStreamWaitEvent(s_side, s_ev_fork, 0);
    k_detect<<<1, 32, 0, s_side>>>(ei);
    cudaEventRecord(s_ev_det, s_side);
    k_prep<<<129, 256, 0, s_side>>>(b1, ga1, be1, rm1, rv1,
                                    b2, ga2, be2, rm2, rv2, W1, W2);
    cudaEventRecord(s_ev_prep, s_side);

    // main: zero -> (wait detect) -> count -> scan1
    k_zero<<<gridN, TPB>>>();
    cudaStreamWaitEvent(0, s_ev_det, 0);
    k_count<<<gridE, TPB>>>(ei);
    k_scan1<<<SCAN_NB, SCAN_B>>>();          // produces g_dinv + block sums

    // fork CSR tail (scan2/scan3/fill) to side; main runs GEMM1
    cudaEventRecord(s_ev_fork2, 0);
    cudaStreamWaitEvent(s_side, s_ev_fork2, 0);
    k_scan2<<<1, 128, 0, s_side>>>();
    k_scan3<<<SCAN_NB, SCAN_B, 0, s_side>>>();
    k_fill<<<gridE, TPB, 0, s_side>>>(ei);
    cudaEventRecord(s_ev_join, s_side);

    // main: GEMM1 needs g_dinv + g_w1h (prep)
    cudaStreamWaitEvent(0, s_ev_prep, 0);
    k_gemm_tc<0><<<gridTC, TPB, GEMM_SMEM>>>(x);

    // join before aggregation (needs CSR)
    cudaStreamWaitEvent(0, s_ev_join, 0);

    k_agg1<<<gridAgg1, TPB>>>();
    k_gemm_tc<1><<<gridTC, TPB, GEMM_SMEM>>>(nullptr);
    k_agg2<<<gridAgg2, TPB>>>(W3);
    k_agg_out<<<gridN, TPB>>>(b3, out);
}